// round 7
// baseline (speedup 1.0000x reference)
#include <cuda_runtime.h>
#include <cuda_bf16.h>
#include <cstdint>
#include <math.h>

// ---------------------------------------------------------------------------
// Problem constants
// ---------------------------------------------------------------------------
constexpr int L = 4;
constexpr int C = 1024;
constexpr int F = 4096;
constexpr int V = 50304;
constexpr int B = 2;
constexpr int T = 1024;
constexpr int M = B * T;            // 2048 rows
constexpr int CH = 16;              // wkv chunks
constexpr int CL = 64;              // wkv chunk length (CH*CL == T)

// ---------------------------------------------------------------------------
// Converted-weight layout: SAME [K,N] layout as inputs (no transpose).
// ---------------------------------------------------------------------------
constexpr size_t MB1 = size_t(C) * C;         // 1,048,576
constexpr size_t O_WR   = 0;                  // [L][C][C]
constexpr size_t O_WK   = 4 * MB1;
constexpr size_t O_WV   = 8 * MB1;
constexpr size_t O_WO   = 12 * MB1;
constexpr size_t O_WFR  = 16 * MB1;
constexpr size_t O_WFK  = 20 * MB1;           // [L][C][F]
constexpr size_t O_WFV  = 36 * MB1;           // [L][F][C]
constexpr size_t O_HEAD = 52 * MB1;           // [C][V]
constexpr size_t WTOTAL = O_HEAD + size_t(V) * C;

__device__ alignas(16) __nv_bfloat16 g_wt_hi[WTOTAL];
__device__ alignas(16) __nv_bfloat16 g_wt_lo[WTOTAL];

__device__ alignas(16) float g_x   [size_t(M) * C];
__device__ alignas(16) float g_r   [size_t(M) * C];
__device__ alignas(16) float g_k   [size_t(M) * C];
__device__ alignas(16) float g_v   [size_t(M) * C];
__device__ alignas(16) float g_sakv[size_t(M) * C];
__device__ alignas(16) float g_sak [size_t(M) * C];
__device__ alignas(16) __nv_bfloat16 g_xn_hi[size_t(M) * C];
__device__ alignas(16) __nv_bfloat16 g_xn_lo[size_t(M) * C];
__device__ alignas(16) __nv_bfloat16 g_y_hi [size_t(M) * C];
__device__ alignas(16) __nv_bfloat16 g_y_lo [size_t(M) * C];
__device__ alignas(16) __nv_bfloat16 g_kf_hi[size_t(M) * F];
__device__ alignas(16) __nv_bfloat16 g_kf_lo[size_t(M) * F];

// wkv chunk-scan scratch: [B][CH][C]
constexpr int AGG = B * CH * C;    // 32768
__device__ alignas(16) float g_aggFkv[AGG];
__device__ alignas(16) float g_aggFk [AGG];
__device__ alignas(16) float g_aggBkv[AGG];
__device__ alignas(16) float g_aggBk [AGG];
__device__ alignas(16) float g_iniFkv[AGG];
__device__ alignas(16) float g_iniFk [AGG];
__device__ alignas(16) float g_iniBkv[AGG];
__device__ alignas(16) float g_iniBk [AGG];

// ---------------------------------------------------------------------------
// Merged streaming split conversion (one launch).
// ---------------------------------------------------------------------------
constexpr size_t N4_CC = size_t(L) * C * C / 4;
constexpr size_t N4_CF = size_t(L) * C * F / 4;
constexpr size_t N4_HD = size_t(V) * C / 4;
constexpr size_t CV_B0 = N4_CC;
constexpr size_t CV_B1 = CV_B0 + N4_CC;
constexpr size_t CV_B2 = CV_B1 + N4_CC;
constexpr size_t CV_B3 = CV_B2 + N4_CC;
constexpr size_t CV_B4 = CV_B3 + N4_CC;
constexpr size_t CV_B5 = CV_B4 + N4_CF;
constexpr size_t CV_B6 = CV_B5 + N4_CF;
constexpr size_t CV_TOT = CV_B6 + N4_HD;

__global__ __launch_bounds__(256) void convert_all_k(
    const float4* __restrict__ wr, const float4* __restrict__ wk,
    const float4* __restrict__ wv, const float4* __restrict__ wo,
    const float4* __restrict__ wfr, const float4* __restrict__ wfk,
    const float4* __restrict__ wfv, const float4* __restrict__ hd,
    uint2* __restrict__ oh, uint2* __restrict__ ol) {
    size_t stride = (size_t)gridDim.x * blockDim.x;
    for (size_t i = (size_t)blockIdx.x * blockDim.x + threadIdx.x; i < CV_TOT;
         i += stride) {
        const float4* src;
        size_t dst;
        if (i < CV_B0)      { src = wr + i; dst = O_WR  / 4 + i; }
        else if (i < CV_B1) { src = wk  + (i - CV_B0); dst = O_WK  / 4 + (i - CV_B0); }
        else if (i < CV_B2) { src = wv  + (i - CV_B1); dst = O_WV  / 4 + (i - CV_B1); }
        else if (i < CV_B3) { src = wo  + (i - CV_B2); dst = O_WO  / 4 + (i - CV_B2); }
        else if (i < CV_B4) { src = wfr + (i - CV_B3); dst = O_WFR / 4 + (i - CV_B3); }
        else if (i < CV_B5) { src = wfk + (i - CV_B4); dst = O_WFK / 4 + (i - CV_B4); }
        else if (i < CV_B6) { src = wfv + (i - CV_B5); dst = O_WFV / 4 + (i - CV_B5); }
        else                { src = hd  + (i - CV_B6); dst = O_HEAD/ 4 + (i - CV_B6); }
        float4 w = *src;
        union { __nv_bfloat162 h[2]; uint2 u; } H, Lo;
        H.h[0].x = __float2bfloat16(w.x);
        H.h[0].y = __float2bfloat16(w.y);
        H.h[1].x = __float2bfloat16(w.z);
        H.h[1].y = __float2bfloat16(w.w);
        Lo.h[0].x = __float2bfloat16(w.x - __bfloat162float(H.h[0].x));
        Lo.h[0].y = __float2bfloat16(w.y - __bfloat162float(H.h[0].y));
        Lo.h[1].x = __float2bfloat16(w.z - __bfloat162float(H.h[1].x));
        Lo.h[1].y = __float2bfloat16(w.w - __bfloat162float(H.h[1].y));
        oh[dst] = H.u;
        ol[dst] = Lo.u;
    }
}

// ---------------------------------------------------------------------------
// Embedding gather
// ---------------------------------------------------------------------------
__global__ void embed_k(const int* __restrict__ idx,
                        const float* __restrict__ emb,
                        float* __restrict__ x) {
    int row = blockIdx.x;
    int id = idx[row];
    const float4* src = (const float4*)(emb + (size_t)id * C);
    float4* dst = (float4*)(x + (size_t)row * C);
    for (int i = threadIdx.x; i < C / 4; i += blockDim.x) dst[i] = src[i];
}

// ---------------------------------------------------------------------------
// LayerNorm -> split bf16 output
// ---------------------------------------------------------------------------
__global__ __launch_bounds__(256) void layernorm_k(const float* __restrict__ x,
                                                   const float* __restrict__ w,
                                                   const float* __restrict__ b,
                                                   __nv_bfloat16* __restrict__ out_hi,
                                                   __nv_bfloat16* __restrict__ out_lo) {
    __shared__ float red[256];
    int row = blockIdx.x;
    const float* xr = x + (size_t)row * C;
    float v[4];
    float s = 0.f;
#pragma unroll
    for (int i = 0; i < 4; i++) { v[i] = xr[threadIdx.x + 256 * i]; s += v[i]; }
    red[threadIdx.x] = s;
    __syncthreads();
    for (int o = 128; o > 0; o >>= 1) {
        if (threadIdx.x < o) red[threadIdx.x] += red[threadIdx.x + o];
        __syncthreads();
    }
    float mu = red[0] * (1.f / C);
    __syncthreads();
    float s2 = 0.f;
#pragma unroll
    for (int i = 0; i < 4; i++) { float d = v[i] - mu; s2 += d * d; }
    red[threadIdx.x] = s2;
    __syncthreads();
    for (int o = 128; o > 0; o >>= 1) {
        if (threadIdx.x < o) red[threadIdx.x] += red[threadIdx.x + o];
        __syncthreads();
    }
    float rstd = rsqrtf(red[0] * (1.f / C) + 1e-5f);
#pragma unroll
    for (int i = 0; i < 4; i++) {
        int c = threadIdx.x + 256 * i;
        float o = (v[i] - mu) * rstd * w[c] + b[c];
        __nv_bfloat16 h = __float2bfloat16(o);
        size_t off = (size_t)row * C + c;
        out_hi[off] = h;
        out_lo[off] = __float2bfloat16(o - __bfloat162float(h));
    }
}

// ---------------------------------------------------------------------------
// Split-bf16 tensor-core GEMM via mma.sync — 64x128 CTA tile, 2 CTAs/SM.
//   256 threads / 8 warps, warp grid 2(m) x 4(n), warp tile 32x32.
//   3 MMA terms: Ah*Bh + Ah*Bl + Al*Bh (fp32 acc).
//   EPI 0 plain | 1 sigmoid | 2 relu^2->bf16 split | 3 res+acc | 4 res+gate*acc
// 4-stage cp.async pipeline; 110,592 B smem -> two CTAs co-resident per SM.
// ---------------------------------------------------------------------------
constexpr int BM = 64;
constexpr int BK = 32;
constexpr int SSTRA = 40;                     // A row pad (80B)
constexpr int SSTRB = 136;                    // B row pad (272B)
constexpr int TA = BM * SSTRA * 2;            // 5120 B
constexpr int TB = BK * SSTRB * 2;            // 8704 B
constexpr int OFF_AH = 0;
constexpr int OFF_AL = TA;
constexpr int OFF_BH = 2 * TA;
constexpr int OFF_BL = 2 * TA + TB;
constexpr int STAGEB = 2 * TA + 2 * TB;       // 27648 B
constexpr int NSTAGE = 4;
constexpr int GEMM_SMEM = NSTAGE * STAGEB;    // 110592 B
constexpr int GTHREADS = 256;

__device__ __forceinline__ uint32_t smem_u32(const void* p) {
    uint32_t a;
    asm("{ .reg .u64 t; cvta.to.shared.u64 t, %1; cvt.u32.u64 %0, t; }"
        : "=r"(a) : "l"(p));
    return a;
}

__device__ __forceinline__ void ldsm_x4(uint32_t addr, uint32_t& r0, uint32_t& r1,
                                        uint32_t& r2, uint32_t& r3) {
    asm volatile("ldmatrix.sync.aligned.m8n8.x4.shared.b16 {%0,%1,%2,%3}, [%4];"
                 : "=r"(r0), "=r"(r1), "=r"(r2), "=r"(r3) : "r"(addr));
}

__device__ __forceinline__ void ldsm_x4_t(uint32_t addr, uint32_t& r0, uint32_t& r1,
                                          uint32_t& r2, uint32_t& r3) {
    asm volatile("ldmatrix.sync.aligned.m8n8.x4.trans.shared.b16 {%0,%1,%2,%3}, [%4];"
                 : "=r"(r0), "=r"(r1), "=r"(r2), "=r"(r3) : "r"(addr));
}

__device__ __forceinline__ void mma_bf16(float* d, const uint32_t* a,
                                         uint32_t b0, uint32_t b1) {
    asm volatile(
        "mma.sync.aligned.m16n8k16.row.col.f32.bf16.bf16.f32 "
        "{%0,%1,%2,%3}, {%4,%5,%6,%7}, {%8,%9}, {%0,%1,%2,%3};"
        : "+f"(d[0]), "+f"(d[1]), "+f"(d[2]), "+f"(d[3])
        : "r"(a[0]), "r"(a[1]), "r"(a[2]), "r"(a[3]), "r"(b0), "r"(b1));
}

__device__ __forceinline__ void cp16(uint32_t sp, const void* gp) {
    asm volatile("cp.async.cg.shared.global [%0], [%1], 16;" :: "r"(sp), "l"(gp));
}

// A tile: 64 rows x 32 k (64B/row). 64 threads: 1 row, 4 cp16 each.
__device__ __forceinline__ void issue_A(uint32_t dst, const __nv_bfloat16* __restrict__ g,
                                        int brow, int K, int k0, int t64) {
    int r = t64;
    const __nv_bfloat16* gp = g + (size_t)(brow + r) * K + k0;
    uint32_t sp = dst + r * (SSTRA * 2);
#pragma unroll
    for (int cc = 0; cc < 4; cc++)
        cp16(sp + cc * 16, gp + cc * 8);
}

// B tile: 32 k-rows x 128 n (256B/row = 16 chunks). 64 threads: 8 chunks each.
__device__ __forceinline__ void issue_B(uint32_t dst, const __nv_bfloat16* __restrict__ g,
                                        int bcol, int N, int k0, int t64) {
    int r = t64 >> 1;
    int c0 = (t64 & 1) * 8;
    const __nv_bfloat16* gp = g + (size_t)(k0 + r) * N + bcol + c0 * 8;
    uint32_t sp = dst + r * (SSTRB * 2) + c0 * 16;
#pragma unroll
    for (int cc = 0; cc < 8; cc++)
        cp16(sp + cc * 16, gp + cc * 8);
}

template <int EPI>
__global__ __launch_bounds__(GTHREADS, 2) void gemm_mma(
    const __nv_bfloat16* __restrict__ Ah, const __nv_bfloat16* __restrict__ Al,
    const __nv_bfloat16* __restrict__ Bh, const __nv_bfloat16* __restrict__ Bl,
    float* __restrict__ Cc,
    __nv_bfloat16* __restrict__ Chi, __nv_bfloat16* __restrict__ Clo,
    const float* __restrict__ res, const float* __restrict__ gate,
    int N, int K) {
    extern __shared__ __align__(128) char sm[];
    uint32_t smem = smem_u32(sm);
    int tid = threadIdx.x;
    int wid = tid >> 5;
    int lane = tid & 31;
    int brow = blockIdx.x * BM;
    int bcol = blockIdx.y * 128;
    int warp_m = wid & 1;          // 0..1 (32 rows each)
    int warp_n = wid >> 1;         // 0..3 (32 cols each)

    int tile_id = tid >> 6;        // 0:Ah 1:Al 2:Bh 3:Bl
    int t64 = tid & 63;

    float acc[2][4][4];
#pragma unroll
    for (int i = 0; i < 2; i++)
#pragma unroll
        for (int j = 0; j < 4; j++)
#pragma unroll
            for (int q = 0; q < 4; q++) acc[i][j][q] = 0.f;

    int nch = K >> 5;              // BK = 32

    // prologue: stages 0 .. NSTAGE-2
#pragma unroll
    for (int s = 0; s < NSTAGE - 1; s++) {
        uint32_t sb = smem + s * STAGEB;
        if (tile_id == 0)      issue_A(sb + OFF_AH, Ah, brow, K, s * BK, t64);
        else if (tile_id == 1) issue_A(sb + OFF_AL, Al, brow, K, s * BK, t64);
        else if (tile_id == 2) issue_B(sb + OFF_BH, Bh, bcol, N, s * BK, t64);
        else                   issue_B(sb + OFF_BL, Bl, bcol, N, s * BK, t64);
        asm volatile("cp.async.commit_group;");
    }

    int a_r = (lane & 15);                    // A: row within 16-row block
    int a_k = ((lane >> 4) << 3);             // A: 0 or 8 k-offset
    int b_kr = (lane & 15);                   // B: k-row within 16
    int b_nf = ((lane >> 4) << 3);            // B: 0 or 8 n-offset

#pragma unroll 1
    for (int c = 0; c < nch; c++) {
        asm volatile("cp.async.wait_group 2;");   // NSTAGE-2
        __syncthreads();
        if (c + NSTAGE - 1 < nch) {
            uint32_t sb = smem + ((c + NSTAGE - 1) % NSTAGE) * STAGEB;
            int k0 = (c + NSTAGE - 1) * BK;
            if (tile_id == 0)      issue_A(sb + OFF_AH, Ah, brow, K, k0, t64);
            else if (tile_id == 1) issue_A(sb + OFF_AL, Al, brow, K, k0, t64);
            else if (tile_id == 2) issue_B(sb + OFF_BH, Bh, bcol, N, k0, t64);
            else                   issue_B(sb + OFF_BL, Bl, bcol, N, k0, t64);
        }
        asm volatile("cp.async.commit_group;");   // empty commit keeps count exact

        uint32_t sbase = smem + (c % NSTAGE) * STAGEB;
#pragma unroll
        for (int ks = 0; ks < 2; ks++) {
            int kk = ks * 16;
            uint32_t ah[2][4], al[2][4], bh[4][2], bl[4][2];
            uint32_t acol = (uint32_t)(kk + a_k) * 2;
#pragma unroll
            for (int mi = 0; mi < 2; mi++) {
                uint32_t ad = sbase + OFF_AH +
                              (warp_m * 32 + mi * 16 + a_r) * (SSTRA * 2) + acol;
                ldsm_x4(ad, ah[mi][0], ah[mi][1], ah[mi][2], ah[mi][3]);
                ldsm_x4(ad + TA, al[mi][0], al[mi][1], al[mi][2], al[mi][3]);
            }
#pragma unroll
            for (int nj = 0; nj < 2; nj++) {
                uint32_t bd = sbase + OFF_BH + (kk + b_kr) * (SSTRB * 2) +
                              (warp_n * 32 + nj * 16 + b_nf) * 2;
                uint32_t r0, r1, r2, r3;
                ldsm_x4_t(bd, r0, r1, r2, r3);
                bh[nj * 2][0] = r0;     bh[nj * 2][1] = r1;
                bh[nj * 2 + 1][0] = r2; bh[nj * 2 + 1][1] = r3;
                ldsm_x4_t(bd + TB, r0, r1, r2, r3);
                bl[nj * 2][0] = r0;     bl[nj * 2][1] = r1;
                bl[nj * 2 + 1][0] = r2; bl[nj * 2 + 1][1] = r3;
            }
#pragma unroll
            for (int mi = 0; mi < 2; mi++)
#pragma unroll
                for (int ni = 0; ni < 4; ni++)
                    mma_bf16(acc[mi][ni], ah[mi], bh[ni][0], bh[ni][1]);
#pragma unroll
            for (int mi = 0; mi < 2; mi++)
#pragma unroll
                for (int ni = 0; ni < 4; ni++)
                    mma_bf16(acc[mi][ni], ah[mi], bl[ni][0], bl[ni][1]);
#pragma unroll
            for (int mi = 0; mi < 2; mi++)
#pragma unroll
                for (int ni = 0; ni < 4; ni++)
                    mma_bf16(acc[mi][ni], al[mi], bh[ni][0], bh[ni][1]);
        }
    }

    int qrow = lane >> 2;
    int qcol = (lane & 3) * 2;
#pragma unroll
    for (int mi = 0; mi < 2; mi++) {
#pragma unroll
        for (int h = 0; h < 2; h++) {
            int row = brow + warp_m * 32 + mi * 16 + qrow + h * 8;
#pragma unroll
            for (int ni = 0; ni < 4; ni++) {
                int col = bcol + warp_n * 32 + ni * 8 + qcol;
                size_t off = (size_t)row * N + col;
                float o0 = acc[mi][ni][h * 2];
                float o1 = acc[mi][ni][h * 2 + 1];
                if (EPI == 1) {
                    o0 = 1.f / (1.f + expf(-o0));
                    o1 = 1.f / (1.f + expf(-o1));
                } else if (EPI == 3) {
                    const float2 rv = *(const float2*)(res + off);
                    o0 += rv.x; o1 += rv.y;
                } else if (EPI == 4) {
                    const float2 rv = *(const float2*)(res + off);
                    const float2 gv = *(const float2*)(gate + off);
                    o0 = rv.x + gv.x * o0;
                    o1 = rv.y + gv.y * o1;
                }
                if (EPI == 2) {
                    o0 = fmaxf(o0, 0.f); o0 *= o0;
                    o1 = fmaxf(o1, 0.f); o1 *= o1;
                    __nv_bfloat16 h0 = __float2bfloat16(o0);
                    __nv_bfloat16 h1 = __float2bfloat16(o1);
                    __nv_bfloat162 hp; hp.x = h0; hp.y = h1;
                    __nv_bfloat162 lp;
                    lp.x = __float2bfloat16(o0 - __bfloat162float(h0));
                    lp.y = __float2bfloat16(o1 - __bfloat162float(h1));
                    *(__nv_bfloat162*)(Chi + off) = hp;
                    *(__nv_bfloat162*)(Clo + off) = lp;
                } else {
                    float2 ov = make_float2(o0, o1);
                    *(float2*)(Cc + off) = ov;
                }
            }
        }
    }
}

// ---------------------------------------------------------------------------
// Chunk-parallel bidirectional WKV (3 kernels).
// ---------------------------------------------------------------------------
__global__ __launch_bounds__(256) void wkv_agg_k(
    const float* __restrict__ k, const float* __restrict__ v,
    const float* __restrict__ w,
    float* __restrict__ aFkv, float* __restrict__ aFk,
    float* __restrict__ aBkv, float* __restrict__ aBk) {
    int gid = blockIdx.x * blockDim.x + threadIdx.x;   // 0 .. B*CH*C-1
    int c = gid & (C - 1);
    int ch = (gid >> 10) & (CH - 1);
    int b = gid >> 14;
    float d = expf(-expf(w[c]));
    size_t base = (size_t)b * T * C + (size_t)ch * CL * C + c;

    float fkv = 0.f, fk = 0.f, bkv = 0.f, bk = 0.f, pw = 1.f;
#pragma unroll 4
    for (int i = 0; i < CL; i++) {
        size_t o = base + (size_t)i * C;
        float ek = expf(k[o]);
        float kv = ek * v[o];
        fkv = fkv * d + kv;
        fk  = fk  * d + ek;
        bkv += kv * pw;
        bk  += ek * pw;
        pw *= d;
    }
    aFkv[gid] = fkv; aFk[gid] = fk;
    aBkv[gid] = bkv; aBk[gid] = bk;
}

__global__ __launch_bounds__(256) void wkv_scan_k(
    const float* __restrict__ w,
    const float* __restrict__ aFkv, const float* __restrict__ aFk,
    const float* __restrict__ aBkv, const float* __restrict__ aBk,
    float* __restrict__ iFkv, float* __restrict__ iFk,
    float* __restrict__ iBkv, float* __restrict__ iBk) {
    int gid = blockIdx.x * blockDim.x + threadIdx.x;   // 0 .. B*C-1
    int c = gid & (C - 1);
    int b = gid >> 10;
    float D = expf(-(float)CL * expf(w[c]));           // d^CL
    int base = b * CH * C + c;

    float skv = 0.f, sk = 0.f;
#pragma unroll
    for (int ch = 0; ch < CH; ch++) {
        int ai = base + ch * C;
        iFkv[ai] = skv; iFk[ai] = sk;
        skv = skv * D + aFkv[ai];
        sk  = sk  * D + aFk[ai];
    }
    skv = 0.f; sk = 0.f;
#pragma unroll
    for (int ch = CH - 1; ch >= 0; ch--) {
        int ai = base + ch * C;
        iBkv[ai] = skv; iBk[ai] = sk;
        skv = skv * D + aBkv[ai];
        sk  = sk  * D + aBk[ai];
    }
}

__global__ __launch_bounds__(256) void wkv_apply_k(
    const float* __restrict__ r, const float* __restrict__ k,
    const float* __restrict__ v, const float* __restrict__ w,
    const float* __restrict__ u,
    const float* __restrict__ iFkv, const float* __restrict__ iFk,
    const float* __restrict__ iBkv, const float* __restrict__ iBk,
    __nv_bfloat16* __restrict__ y_hi, __nv_bfloat16* __restrict__ y_lo,
    float* __restrict__ sakv, float* __restrict__ sak) {
    int gid = blockIdx.x * blockDim.x + threadIdx.x;   // 0 .. B*CH*C-1
    int c = gid & (C - 1);
    int ch = (gid >> 10) & (CH - 1);
    int b = gid >> 14;
    float d = expf(-expf(w[c]));
    float eu = expf(u[c]);
    size_t base = (size_t)b * T * C + (size_t)ch * CL * C + c;

    float fkv = iFkv[gid], fk = iFk[gid];
#pragma unroll 4
    for (int i = 0; i < CL; i++) {
        size_t o = base + (size_t)i * C;
        float ek = expf(k[o]);
        float kv = ek * v[o];
        sakv[o] = fkv;
        sak[o]  = fk;
        fkv = fkv * d + kv;
        fk  = fk  * d + ek;
    }
    float bkv = iBkv[gid], bk = iBk[gid];
#pragma unroll 4
    for (int i = CL - 1; i >= 0; i--) {
        size_t o = base + (size_t)i * C;
        float vv = v[o];
        float ek = expf(k[o]);
        float kv = ek * vv;
        float num = sakv[o] + bkv + eu * vv;
        float den = sak[o]  + bk  + eu;
        float yv = r[o] * num / (den + 1e-8f);
        __nv_bfloat16 h = __float2bfloat16(yv);
        y_hi[o] = h;
        y_lo[o] = __float2bfloat16(yv - __bfloat162float(h));
        bkv = bkv * d + kv;
        bk  = bk  * d + ek;
    }
}

// ---------------------------------------------------------------------------
// Host launch
// ---------------------------------------------------------------------------
extern "C" void kernel_launch(void* const* d_in, const int* in_sizes, int n_in,
                              void* d_out, int out_size) {
    const int*   idx     = (const int*)  d_in[0];
    const float* emb     = (const float*)d_in[1];
    const float* ln1_w   = (const float*)d_in[2];
    const float* ln1_b   = (const float*)d_in[3];
    const float* Wr      = (const float*)d_in[4];
    const float* Wk      = (const float*)d_in[5];
    const float* Wv      = (const float*)d_in[6];
    const float* w_decay = (const float*)d_in[7];
    const float* u_bonus = (const float*)d_in[8];
    const float* Wo      = (const float*)d_in[9];
    const float* ln2_w   = (const float*)d_in[10];
    const float* ln2_b   = (const float*)d_in[11];
    const float* Wfk     = (const float*)d_in[12];
    const float* Wfv     = (const float*)d_in[13];
    const float* Wfr     = (const float*)d_in[14];
    const float* lnout_w = (const float*)d_in[15];
    const float* lnout_b = (const float*)d_in[16];
    const float* head_W  = (const float*)d_in[17];
    float* out = (float*)d_out;

    float *x, *r, *k, *v, *sa, *sb;
    float *aFkv, *aFk, *aBkv, *aBk, *iFkv, *iFk, *iBkv, *iBk;
    __nv_bfloat16 *wth, *wtl, *xnh, *xnl, *yh, *yl, *kfh, *kfl;
    cudaGetSymbolAddress((void**)&x,    g_x);
    cudaGetSymbolAddress((void**)&r,    g_r);
    cudaGetSymbolAddress((void**)&k,    g_k);
    cudaGetSymbolAddress((void**)&v,    g_v);
    cudaGetSymbolAddress((void**)&sa,   g_sakv);
    cudaGetSymbolAddress((void**)&sb,   g_sak);
    cudaGetSymbolAddress((void**)&wth,  g_wt_hi);
    cudaGetSymbolAddress((void**)&wtl,  g_wt_lo);
    cudaGetSymbolAddress((void**)&xnh,  g_xn_hi);
    cudaGetSymbolAddress((void**)&xnl,  g_xn_lo);
    cudaGetSymbolAddress((void**)&yh,   g_y_hi);
    cudaGetSymbolAddress((void**)&yl,   g_y_lo);
    cudaGetSymbolAddress((void**)&kfh,  g_kf_hi);
    cudaGetSymbolAddress((void**)&kfl,  g_kf_lo);
    cudaGetSymbolAddress((void**)&aFkv, g_aggFkv);
    cudaGetSymbolAddress((void**)&aFk,  g_aggFk);
    cudaGetSymbolAddress((void**)&aBkv, g_aggBkv);
    cudaGetSymbolAddress((void**)&aBk,  g_aggBk);
    cudaGetSymbolAddress((void**)&iFkv, g_iniFkv);
    cudaGetSymbolAddress((void**)&iFk,  g_iniFk);
    cudaGetSymbolAddress((void**)&iBkv, g_iniBkv);
    cudaGetSymbolAddress((void**)&iBk,  g_iniBk);

    cudaFuncSetAttribute(gemm_mma<0>, cudaFuncAttributeMaxDynamicSharedMemorySize, GEMM_SMEM);
    cudaFuncSetAttribute(gemm_mma<1>, cudaFuncAttributeMaxDynamicSharedMemorySize, GEMM_SMEM);
    cudaFuncSetAttribute(gemm_mma<2>, cudaFuncAttributeMaxDynamicSharedMemorySize, GEMM_SMEM);
    cudaFuncSetAttribute(gemm_mma<3>, cudaFuncAttributeMaxDynamicSharedMemorySize, GEMM_SMEM);
    cudaFuncSetAttribute(gemm_mma<4>, cudaFuncAttributeMaxDynamicSharedMemorySize, GEMM_SMEM);

    convert_all_k<<<4096, 256>>>((const float4*)Wr, (const float4*)Wk,
                                 (const float4*)Wv, (const float4*)Wo,
                                 (const float4*)Wfr, (const float4*)Wfk,
                                 (const float4*)Wfv, (const float4*)head_W,
                                 (uint2*)wth, (uint2*)wtl);

    embed_k<<<M, 256>>>(idx, emb, x);

    dim3 gCCg(M / BM, C / 128);    // 32 x 8  = 256 CTAs
    dim3 gCFg(M / BM, F / 128);    // 32 x 32 = 1024 CTAs
    dim3 gCVg(M / BM, V / 128);    // 32 x 393

    for (int l = 0; l < L; l++) {
        size_t wcc = (size_t)l * C * C;
        size_t wcf = (size_t)l * C * F;
        const float* l1w = ln1_w + (size_t)l * C;
        const float* l1b = ln1_b + (size_t)l * C;
        const float* wd  = w_decay + (size_t)l * C;
        const float* ub  = u_bonus + (size_t)l * C;
        const float* l2w = ln2_w + (size_t)l * C;
        const float* l2b = ln2_b + (size_t)l * C;

        // time-mix
        layernorm_k<<<M, 256>>>(x, l1w, l1b, xnh, xnl);
        gemm_mma<1><<<gCCg, GTHREADS, GEMM_SMEM>>>(xnh, xnl, wth + O_WR + wcc, wtl + O_WR + wcc,
                                                   r, nullptr, nullptr, nullptr, nullptr, C, C);
        gemm_mma<0><<<gCCg, GTHREADS, GEMM_SMEM>>>(xnh, xnl, wth + O_WK + wcc, wtl + O_WK + wcc,
                                                   k, nullptr, nullptr, nullptr, nullptr, C, C);
        gemm_mma<0><<<gCCg, GTHREADS, GEMM_SMEM>>>(xnh, xnl, wth + O_WV + wcc, wtl + O_WV + wcc,
                                                   v, nullptr, nullptr, nullptr, nullptr, C, C);
        wkv_agg_k<<<(B * CH * C) / 256, 256>>>(k, v, wd, aFkv, aFk, aBkv, aBk);
        wkv_scan_k<<<(B * C) / 256, 256>>>(wd, aFkv, aFk, aBkv, aBk,
                                           iFkv, iFk, iBkv, iBk);
        wkv_apply_k<<<(B * CH * C) / 256, 256>>>(r, k, v, wd, ub,
                                                 iFkv, iFk, iBkv, iBk,
                                                 yh, yl, sa, sb);
        gemm_mma<3><<<gCCg, GTHREADS, GEMM_SMEM>>>(yh, yl, wth + O_WO + wcc, wtl + O_WO + wcc,
                                                   x, nullptr, nullptr, x, nullptr, C, C);

        // channel-mix
        layernorm_k<<<M, 256>>>(x, l2w, l2b, xnh, xnl);
        gemm_mma<1><<<gCCg, GTHREADS, GEMM_SMEM>>>(xnh, xnl, wth + O_WFR + wcc, wtl + O_WFR + wcc,
                                                   r, nullptr, nullptr, nullptr, nullptr, C, C);
        gemm_mma<2><<<gCFg, GTHREADS, GEMM_SMEM>>>(xnh, xnl, wth + O_WFK + wcf, wtl + O_WFK + wcf,
                                                   nullptr, kfh, kfl, nullptr, nullptr, F, C);
        gemm_mma<4><<<gCCg, GTHREADS, GEMM_SMEM>>>(kfh, kfl, wth + O_WFV + wcf, wtl + O_WFV + wcf,
                                                   x, nullptr, nullptr, x, r, C, F);
    }

    layernorm_k<<<M, 256>>>(x, lnout_w, lnout_b, xnh, xnl);
    gemm_mma<0><<<gCVg, GTHREADS, GEMM_SMEM>>>(xnh, xnl, wth + O_HEAD, wtl + O_HEAD,
                                               out, nullptr, nullptr, nullptr, nullptr, V, C);
}

// round 8
// speedup vs baseline: 1.0118x; 1.0118x over previous
#include <cuda_runtime.h>
#include <cuda_bf16.h>
#include <cstdint>
#include <math.h>

// ---------------------------------------------------------------------------
// Problem constants
// ---------------------------------------------------------------------------
constexpr int L = 4;
constexpr int C = 1024;
constexpr int F = 4096;
constexpr int V = 50304;
constexpr int B = 2;
constexpr int T = 1024;
constexpr int M = B * T;            // 2048 rows
constexpr int CH = 16;              // wkv chunks
constexpr int CL = 64;              // wkv chunk length (CH*CL == T)

// ---------------------------------------------------------------------------
// Converted-weight layout: SAME [K,N] layout as inputs (no transpose).
// ---------------------------------------------------------------------------
constexpr size_t MB1 = size_t(C) * C;         // 1,048,576
constexpr size_t O_WR   = 0;                  // [L][C][C]
constexpr size_t O_WK   = 4 * MB1;
constexpr size_t O_WV   = 8 * MB1;
constexpr size_t O_WO   = 12 * MB1;
constexpr size_t O_WFR  = 16 * MB1;
constexpr size_t O_WFK  = 20 * MB1;           // [L][C][F]
constexpr size_t O_WFV  = 36 * MB1;           // [L][F][C]
constexpr size_t O_HEAD = 52 * MB1;           // [C][V]
constexpr size_t WTOTAL = O_HEAD + size_t(V) * C;

__device__ alignas(16) __nv_bfloat16 g_wt_hi[WTOTAL];
__device__ alignas(16) __nv_bfloat16 g_wt_lo[WTOTAL];

__device__ alignas(16) float g_x   [size_t(M) * C];
__device__ alignas(16) float g_r   [size_t(M) * C];
__device__ alignas(16) float g_k   [size_t(M) * C];
__device__ alignas(16) float g_v   [size_t(M) * C];
__device__ alignas(16) float g_sakv[size_t(M) * C];
__device__ alignas(16) float g_sak [size_t(M) * C];
__device__ alignas(16) __nv_bfloat16 g_xn_hi[size_t(M) * C];
__device__ alignas(16) __nv_bfloat16 g_xn_lo[size_t(M) * C];
__device__ alignas(16) __nv_bfloat16 g_y_hi [size_t(M) * C];
__device__ alignas(16) __nv_bfloat16 g_y_lo [size_t(M) * C];
__device__ alignas(16) __nv_bfloat16 g_kf_hi[size_t(M) * F];
__device__ alignas(16) __nv_bfloat16 g_kf_lo[size_t(M) * F];

// wkv chunk-scan scratch: [B][CH][C]
constexpr int AGG = B * CH * C;    // 32768
__device__ alignas(16) float g_aggFkv[AGG];
__device__ alignas(16) float g_aggFk [AGG];
__device__ alignas(16) float g_aggBkv[AGG];
__device__ alignas(16) float g_aggBk [AGG];
__device__ alignas(16) float g_iniFkv[AGG];
__device__ alignas(16) float g_iniFk [AGG];
__device__ alignas(16) float g_iniBkv[AGG];
__device__ alignas(16) float g_iniBk [AGG];

// ---------------------------------------------------------------------------
// Merged streaming split conversion (one launch).
// ---------------------------------------------------------------------------
constexpr size_t N4_CC = size_t(L) * C * C / 4;
constexpr size_t N4_CF = size_t(L) * C * F / 4;
constexpr size_t N4_HD = size_t(V) * C / 4;
constexpr size_t CV_B0 = N4_CC;
constexpr size_t CV_B1 = CV_B0 + N4_CC;
constexpr size_t CV_B2 = CV_B1 + N4_CC;
constexpr size_t CV_B3 = CV_B2 + N4_CC;
constexpr size_t CV_B4 = CV_B3 + N4_CC;
constexpr size_t CV_B5 = CV_B4 + N4_CF;
constexpr size_t CV_B6 = CV_B5 + N4_CF;
constexpr size_t CV_TOT = CV_B6 + N4_HD;

__global__ __launch_bounds__(256) void convert_all_k(
    const float4* __restrict__ wr, const float4* __restrict__ wk,
    const float4* __restrict__ wv, const float4* __restrict__ wo,
    const float4* __restrict__ wfr, const float4* __restrict__ wfk,
    const float4* __restrict__ wfv, const float4* __restrict__ hd,
    uint2* __restrict__ oh, uint2* __restrict__ ol) {
    size_t stride = (size_t)gridDim.x * blockDim.x;
    for (size_t i = (size_t)blockIdx.x * blockDim.x + threadIdx.x; i < CV_TOT;
         i += stride) {
        const float4* src;
        size_t dst;
        if (i < CV_B0)      { src = wr + i; dst = O_WR  / 4 + i; }
        else if (i < CV_B1) { src = wk  + (i - CV_B0); dst = O_WK  / 4 + (i - CV_B0); }
        else if (i < CV_B2) { src = wv  + (i - CV_B1); dst = O_WV  / 4 + (i - CV_B1); }
        else if (i < CV_B3) { src = wo  + (i - CV_B2); dst = O_WO  / 4 + (i - CV_B2); }
        else if (i < CV_B4) { src = wfr + (i - CV_B3); dst = O_WFR / 4 + (i - CV_B3); }
        else if (i < CV_B5) { src = wfk + (i - CV_B4); dst = O_WFK / 4 + (i - CV_B4); }
        else if (i < CV_B6) { src = wfv + (i - CV_B5); dst = O_WFV / 4 + (i - CV_B5); }
        else                { src = hd  + (i - CV_B6); dst = O_HEAD/ 4 + (i - CV_B6); }
        float4 w = *src;
        union { __nv_bfloat162 h[2]; uint2 u; } H, Lo;
        H.h[0].x = __float2bfloat16(w.x);
        H.h[0].y = __float2bfloat16(w.y);
        H.h[1].x = __float2bfloat16(w.z);
        H.h[1].y = __float2bfloat16(w.w);
        Lo.h[0].x = __float2bfloat16(w.x - __bfloat162float(H.h[0].x));
        Lo.h[0].y = __float2bfloat16(w.y - __bfloat162float(H.h[0].y));
        Lo.h[1].x = __float2bfloat16(w.z - __bfloat162float(H.h[1].x));
        Lo.h[1].y = __float2bfloat16(w.w - __bfloat162float(H.h[1].y));
        oh[dst] = H.u;
        ol[dst] = Lo.u;
    }
}

// ---------------------------------------------------------------------------
// Embedding gather
// ---------------------------------------------------------------------------
__global__ void embed_k(const int* __restrict__ idx,
                        const float* __restrict__ emb,
                        float* __restrict__ x) {
    int row = blockIdx.x;
    int id = idx[row];
    const float4* src = (const float4*)(emb + (size_t)id * C);
    float4* dst = (float4*)(x + (size_t)row * C);
    for (int i = threadIdx.x; i < C / 4; i += blockDim.x) dst[i] = src[i];
}

// ---------------------------------------------------------------------------
// LayerNorm -> split bf16 output
// ---------------------------------------------------------------------------
__global__ __launch_bounds__(256) void layernorm_k(const float* __restrict__ x,
                                                   const float* __restrict__ w,
                                                   const float* __restrict__ b,
                                                   __nv_bfloat16* __restrict__ out_hi,
                                                   __nv_bfloat16* __restrict__ out_lo) {
    __shared__ float red[256];
    int row = blockIdx.x;
    const float* xr = x + (size_t)row * C;
    float v[4];
    float s = 0.f;
#pragma unroll
    for (int i = 0; i < 4; i++) { v[i] = xr[threadIdx.x + 256 * i]; s += v[i]; }
    red[threadIdx.x] = s;
    __syncthreads();
    for (int o = 128; o > 0; o >>= 1) {
        if (threadIdx.x < o) red[threadIdx.x] += red[threadIdx.x + o];
        __syncthreads();
    }
    float mu = red[0] * (1.f / C);
    __syncthreads();
    float s2 = 0.f;
#pragma unroll
    for (int i = 0; i < 4; i++) { float d = v[i] - mu; s2 += d * d; }
    red[threadIdx.x] = s2;
    __syncthreads();
    for (int o = 128; o > 0; o >>= 1) {
        if (threadIdx.x < o) red[threadIdx.x] += red[threadIdx.x + o];
        __syncthreads();
    }
    float rstd = rsqrtf(red[0] * (1.f / C) + 1e-5f);
#pragma unroll
    for (int i = 0; i < 4; i++) {
        int c = threadIdx.x + 256 * i;
        float o = (v[i] - mu) * rstd * w[c] + b[c];
        __nv_bfloat16 h = __float2bfloat16(o);
        size_t off = (size_t)row * C + c;
        out_hi[off] = h;
        out_lo[off] = __float2bfloat16(o - __bfloat162float(h));
    }
}

// ---------------------------------------------------------------------------
// Split-bf16 tensor-core GEMM via mma.sync — 512 threads / 16 warps.
//   CTA tile 128x128, stage depth BK=64 (one barrier per 64 K), warp grid
//   4(m) x 4(n), warp tile 32x32.  3 MMA terms: Ah*Bh + Ah*Bl + Al*Bh.
//   EPI 0 plain | 1 sigmoid | 2 relu^2->bf16 split | 3 res+acc | 4 res+gate*acc
// 3-stage cp.async pipeline (215,040 B smem, 1 CTA/SM).
// ---------------------------------------------------------------------------
constexpr int BK = 64;
constexpr int SSTRA = 72;                     // A row pad: 64 elems -> 144B
constexpr int SSTRB = 136;                    // B row pad (272B)
constexpr int TA = 128 * SSTRA * 2;           // 18432 B
constexpr int TB = BK * SSTRB * 2;            // 17408 B
constexpr int OFF_AH = 0;
constexpr int OFF_AL = TA;
constexpr int OFF_BH = 2 * TA;
constexpr int OFF_BL = 2 * TA + TB;
constexpr int STAGEB = 2 * TA + 2 * TB;       // 71680 B
constexpr int NSTAGE = 3;
constexpr int GEMM_SMEM = NSTAGE * STAGEB;    // 215040 B
constexpr int GTHREADS = 512;

__device__ __forceinline__ uint32_t smem_u32(const void* p) {
    uint32_t a;
    asm("{ .reg .u64 t; cvta.to.shared.u64 t, %1; cvt.u32.u64 %0, t; }"
        : "=r"(a) : "l"(p));
    return a;
}

__device__ __forceinline__ void ldsm_x4(uint32_t addr, uint32_t& r0, uint32_t& r1,
                                        uint32_t& r2, uint32_t& r3) {
    asm volatile("ldmatrix.sync.aligned.m8n8.x4.shared.b16 {%0,%1,%2,%3}, [%4];"
                 : "=r"(r0), "=r"(r1), "=r"(r2), "=r"(r3) : "r"(addr));
}

__device__ __forceinline__ void ldsm_x4_t(uint32_t addr, uint32_t& r0, uint32_t& r1,
                                          uint32_t& r2, uint32_t& r3) {
    asm volatile("ldmatrix.sync.aligned.m8n8.x4.trans.shared.b16 {%0,%1,%2,%3}, [%4];"
                 : "=r"(r0), "=r"(r1), "=r"(r2), "=r"(r3) : "r"(addr));
}

__device__ __forceinline__ void mma_bf16(float* d, const uint32_t* a,
                                         uint32_t b0, uint32_t b1) {
    asm volatile(
        "mma.sync.aligned.m16n8k16.row.col.f32.bf16.bf16.f32 "
        "{%0,%1,%2,%3}, {%4,%5,%6,%7}, {%8,%9}, {%0,%1,%2,%3};"
        : "+f"(d[0]), "+f"(d[1]), "+f"(d[2]), "+f"(d[3])
        : "r"(a[0]), "r"(a[1]), "r"(a[2]), "r"(a[3]), "r"(b0), "r"(b1));
}

__device__ __forceinline__ void cp16(uint32_t sp, const void* gp) {
    asm volatile("cp.async.cg.shared.global [%0], [%1], 16;" :: "r"(sp), "l"(gp));
}

// A tile: 128 rows x 64 k (128B/row). 128 threads: 1 row, 8 cp16 each.
__device__ __forceinline__ void issue_A(uint32_t dst, const __nv_bfloat16* __restrict__ g,
                                        int brow, int K, int k0, int t128) {
    int r = t128;
    const __nv_bfloat16* gp = g + (size_t)(brow + r) * K + k0;
    uint32_t sp = dst + r * (SSTRA * 2);
#pragma unroll
    for (int cc = 0; cc < 8; cc++)
        cp16(sp + cc * 16, gp + cc * 8);
}

// B tile: 64 k-rows x 128 n (256B/row = 16 chunks). 128 threads: 8 chunks each.
__device__ __forceinline__ void issue_B(uint32_t dst, const __nv_bfloat16* __restrict__ g,
                                        int bcol, int N, int k0, int t128) {
    int r = t128 >> 1;
    int c0 = (t128 & 1) * 8;
    const __nv_bfloat16* gp = g + (size_t)(k0 + r) * N + bcol + c0 * 8;
    uint32_t sp = dst + r * (SSTRB * 2) + c0 * 16;
#pragma unroll
    for (int cc = 0; cc < 8; cc++)
        cp16(sp + cc * 16, gp + cc * 8);
}

template <int EPI>
__global__ __launch_bounds__(GTHREADS, 1) void gemm_mma(
    const __nv_bfloat16* __restrict__ Ah, const __nv_bfloat16* __restrict__ Al,
    const __nv_bfloat16* __restrict__ Bh, const __nv_bfloat16* __restrict__ Bl,
    float* __restrict__ Cc,
    __nv_bfloat16* __restrict__ Chi, __nv_bfloat16* __restrict__ Clo,
    const float* __restrict__ res, const float* __restrict__ gate,
    int N, int K) {
    extern __shared__ __align__(128) char sm[];
    uint32_t smem = smem_u32(sm);
    int tid = threadIdx.x;
    int wid = tid >> 5;
    int lane = tid & 31;
    int brow = blockIdx.x * 128;
    int bcol = blockIdx.y * 128;
    int warp_m = wid & 3;          // 0..3 (32 rows each)
    int warp_n = wid >> 2;         // 0..3 (32 cols each)

    int tile_id = tid >> 7;        // 0:Ah 1:Al 2:Bh 3:Bl
    int t128 = tid & 127;

    float acc[2][4][4];
#pragma unroll
    for (int i = 0; i < 2; i++)
#pragma unroll
        for (int j = 0; j < 4; j++)
#pragma unroll
            for (int q = 0; q < 4; q++) acc[i][j][q] = 0.f;

    int nch = K >> 6;              // BK = 64

    // prologue: stages 0, 1
#pragma unroll
    for (int s = 0; s < NSTAGE - 1; s++) {
        uint32_t sb = smem + s * STAGEB;
        if (tile_id == 0)      issue_A(sb + OFF_AH, Ah, brow, K, s * BK, t128);
        else if (tile_id == 1) issue_A(sb + OFF_AL, Al, brow, K, s * BK, t128);
        else if (tile_id == 2) issue_B(sb + OFF_BH, Bh, bcol, N, s * BK, t128);
        else                   issue_B(sb + OFF_BL, Bl, bcol, N, s * BK, t128);
        asm volatile("cp.async.commit_group;");
    }

    int a_r = (lane & 15);                    // A: row within 16-row block
    int a_k = ((lane >> 4) << 3);             // A: 0 or 8 k-offset
    int b_kr = (lane & 15);                   // B: k-row within 16
    int b_nf = ((lane >> 4) << 3);            // B: 0 or 8 n-offset

#pragma unroll 1
    for (int c = 0; c < nch; c++) {
        asm volatile("cp.async.wait_group 1;");   // NSTAGE-2
        __syncthreads();
        if (c + NSTAGE - 1 < nch) {
            uint32_t sb = smem + ((c + NSTAGE - 1) % NSTAGE) * STAGEB;
            int k0 = (c + NSTAGE - 1) * BK;
            if (tile_id == 0)      issue_A(sb + OFF_AH, Ah, brow, K, k0, t128);
            else if (tile_id == 1) issue_A(sb + OFF_AL, Al, brow, K, k0, t128);
            else if (tile_id == 2) issue_B(sb + OFF_BH, Bh, bcol, N, k0, t128);
            else                   issue_B(sb + OFF_BL, Bl, bcol, N, k0, t128);
        }
        asm volatile("cp.async.commit_group;");   // empty commit keeps count exact

        uint32_t sbase = smem + (c % NSTAGE) * STAGEB;
#pragma unroll
        for (int ks = 0; ks < 4; ks++) {
            int kk = ks * 16;
            uint32_t ah[2][4], al[2][4], bh[4][2], bl[4][2];
            uint32_t acol = (uint32_t)(kk + a_k) * 2;
#pragma unroll
            for (int mi = 0; mi < 2; mi++) {
                uint32_t ad = sbase + OFF_AH +
                              (warp_m * 32 + mi * 16 + a_r) * (SSTRA * 2) + acol;
                ldsm_x4(ad, ah[mi][0], ah[mi][1], ah[mi][2], ah[mi][3]);
                ldsm_x4(ad + TA, al[mi][0], al[mi][1], al[mi][2], al[mi][3]);
            }
#pragma unroll
            for (int nj = 0; nj < 2; nj++) {
                uint32_t bd = sbase + OFF_BH + (kk + b_kr) * (SSTRB * 2) +
                              (warp_n * 32 + nj * 16 + b_nf) * 2;
                uint32_t r0, r1, r2, r3;
                ldsm_x4_t(bd, r0, r1, r2, r3);
                bh[nj * 2][0] = r0;     bh[nj * 2][1] = r1;
                bh[nj * 2 + 1][0] = r2; bh[nj * 2 + 1][1] = r3;
                ldsm_x4_t(bd + TB, r0, r1, r2, r3);
                bl[nj * 2][0] = r0;     bl[nj * 2][1] = r1;
                bl[nj * 2 + 1][0] = r2; bl[nj * 2 + 1][1] = r3;
            }
#pragma unroll
            for (int mi = 0; mi < 2; mi++)
#pragma unroll
                for (int ni = 0; ni < 4; ni++)
                    mma_bf16(acc[mi][ni], ah[mi], bh[ni][0], bh[ni][1]);
#pragma unroll
            for (int mi = 0; mi < 2; mi++)
#pragma unroll
                for (int ni = 0; ni < 4; ni++)
                    mma_bf16(acc[mi][ni], ah[mi], bl[ni][0], bl[ni][1]);
#pragma unroll
            for (int mi = 0; mi < 2; mi++)
#pragma unroll
                for (int ni = 0; ni < 4; ni++)
                    mma_bf16(acc[mi][ni], al[mi], bh[ni][0], bh[ni][1]);
        }
    }

    int qrow = lane >> 2;
    int qcol = (lane & 3) * 2;
#pragma unroll
    for (int mi = 0; mi < 2; mi++) {
#pragma unroll
        for (int h = 0; h < 2; h++) {
            int row = brow + warp_m * 32 + mi * 16 + qrow + h * 8;
#pragma unroll
            for (int ni = 0; ni < 4; ni++) {
                int col = bcol + warp_n * 32 + ni * 8 + qcol;
                size_t off = (size_t)row * N + col;
                float o0 = acc[mi][ni][h * 2];
                float o1 = acc[mi][ni][h * 2 + 1];
                if (EPI == 1) {
                    o0 = 1.f / (1.f + expf(-o0));
                    o1 = 1.f / (1.f + expf(-o1));
                } else if (EPI == 3) {
                    const float2 rv = *(const float2*)(res + off);
                    o0 += rv.x; o1 += rv.y;
                } else if (EPI == 4) {
                    const float2 rv = *(const float2*)(res + off);
                    const float2 gv = *(const float2*)(gate + off);
                    o0 = rv.x + gv.x * o0;
                    o1 = rv.y + gv.y * o1;
                }
                if (EPI == 2) {
                    o0 = fmaxf(o0, 0.f); o0 *= o0;
                    o1 = fmaxf(o1, 0.f); o1 *= o1;
                    __nv_bfloat16 h0 = __float2bfloat16(o0);
                    __nv_bfloat16 h1 = __float2bfloat16(o1);
                    __nv_bfloat162 hp; hp.x = h0; hp.y = h1;
                    __nv_bfloat162 lp;
                    lp.x = __float2bfloat16(o0 - __bfloat162float(h0));
                    lp.y = __float2bfloat16(o1 - __bfloat162float(h1));
                    *(__nv_bfloat162*)(Chi + off) = hp;
                    *(__nv_bfloat162*)(Clo + off) = lp;
                } else {
                    float2 ov = make_float2(o0, o1);
                    *(float2*)(Cc + off) = ov;
                }
            }
        }
    }
}

// ---------------------------------------------------------------------------
// Chunk-parallel bidirectional WKV (3 kernels).
// ---------------------------------------------------------------------------
__global__ __launch_bounds__(256) void wkv_agg_k(
    const float* __restrict__ k, const float* __restrict__ v,
    const float* __restrict__ w,
    float* __restrict__ aFkv, float* __restrict__ aFk,
    float* __restrict__ aBkv, float* __restrict__ aBk) {
    int gid = blockIdx.x * blockDim.x + threadIdx.x;   // 0 .. B*CH*C-1
    int c = gid & (C - 1);
    int ch = (gid >> 10) & (CH - 1);
    int b = gid >> 14;
    float d = expf(-expf(w[c]));
    size_t base = (size_t)b * T * C + (size_t)ch * CL * C + c;

    float fkv = 0.f, fk = 0.f, bkv = 0.f, bk = 0.f, pw = 1.f;
#pragma unroll 4
    for (int i = 0; i < CL; i++) {
        size_t o = base + (size_t)i * C;
        float ek = expf(k[o]);
        float kv = ek * v[o];
        fkv = fkv * d + kv;
        fk  = fk  * d + ek;
        bkv += kv * pw;
        bk  += ek * pw;
        pw *= d;
    }
    aFkv[gid] = fkv; aFk[gid] = fk;
    aBkv[gid] = bkv; aBk[gid] = bk;
}

__global__ __launch_bounds__(256) void wkv_scan_k(
    const float* __restrict__ w,
    const float* __restrict__ aFkv, const float* __restrict__ aFk,
    const float* __restrict__ aBkv, const float* __restrict__ aBk,
    float* __restrict__ iFkv, float* __restrict__ iFk,
    float* __restrict__ iBkv, float* __restrict__ iBk) {
    int gid = blockIdx.x * blockDim.x + threadIdx.x;   // 0 .. B*C-1
    int c = gid & (C - 1);
    int b = gid >> 10;
    float D = expf(-(float)CL * expf(w[c]));           // d^CL
    int base = b * CH * C + c;

    float skv = 0.f, sk = 0.f;
#pragma unroll
    for (int ch = 0; ch < CH; ch++) {
        int ai = base + ch * C;
        iFkv[ai] = skv; iFk[ai] = sk;
        skv = skv * D + aFkv[ai];
        sk  = sk  * D + aFk[ai];
    }
    skv = 0.f; sk = 0.f;
#pragma unroll
    for (int ch = CH - 1; ch >= 0; ch--) {
        int ai = base + ch * C;
        iBkv[ai] = skv; iBk[ai] = sk;
        skv = skv * D + aBkv[ai];
        sk  = sk  * D + aBk[ai];
    }
}

__global__ __launch_bounds__(256) void wkv_apply_k(
    const float* __restrict__ r, const float* __restrict__ k,
    const float* __restrict__ v, const float* __restrict__ w,
    const float* __restrict__ u,
    const float* __restrict__ iFkv, const float* __restrict__ iFk,
    const float* __restrict__ iBkv, const float* __restrict__ iBk,
    __nv_bfloat16* __restrict__ y_hi, __nv_bfloat16* __restrict__ y_lo,
    float* __restrict__ sakv, float* __restrict__ sak) {
    int gid = blockIdx.x * blockDim.x + threadIdx.x;   // 0 .. B*CH*C-1
    int c = gid & (C - 1);
    int ch = (gid >> 10) & (CH - 1);
    int b = gid >> 14;
    float d = expf(-expf(w[c]));
    float eu = expf(u[c]);
    size_t base = (size_t)b * T * C + (size_t)ch * CL * C + c;

    float fkv = iFkv[gid], fk = iFk[gid];
#pragma unroll 4
    for (int i = 0; i < CL; i++) {
        size_t o = base + (size_t)i * C;
        float ek = expf(k[o]);
        float kv = ek * v[o];
        sakv[o] = fkv;
        sak[o]  = fk;
        fkv = fkv * d + kv;
        fk  = fk  * d + ek;
    }
    float bkv = iBkv[gid], bk = iBk[gid];
#pragma unroll 4
    for (int i = CL - 1; i >= 0; i--) {
        size_t o = base + (size_t)i * C;
        float vv = v[o];
        float ek = expf(k[o]);
        float kv = ek * vv;
        float num = sakv[o] + bkv + eu * vv;
        float den = sak[o]  + bk  + eu;
        float yv = r[o] * num / (den + 1e-8f);
        __nv_bfloat16 h = __float2bfloat16(yv);
        y_hi[o] = h;
        y_lo[o] = __float2bfloat16(yv - __bfloat162float(h));
        bkv = bkv * d + kv;
        bk  = bk  * d + ek;
    }
}

// ---------------------------------------------------------------------------
// Host launch
// ---------------------------------------------------------------------------
extern "C" void kernel_launch(void* const* d_in, const int* in_sizes, int n_in,
                              void* d_out, int out_size) {
    const int*   idx     = (const int*)  d_in[0];
    const float* emb     = (const float*)d_in[1];
    const float* ln1_w   = (const float*)d_in[2];
    const float* ln1_b   = (const float*)d_in[3];
    const float* Wr      = (const float*)d_in[4];
    const float* Wk      = (const float*)d_in[5];
    const float* Wv      = (const float*)d_in[6];
    const float* w_decay = (const float*)d_in[7];
    const float* u_bonus = (const float*)d_in[8];
    const float* Wo      = (const float*)d_in[9];
    const float* ln2_w   = (const float*)d_in[10];
    const float* ln2_b   = (const float*)d_in[11];
    const float* Wfk     = (const float*)d_in[12];
    const float* Wfv     = (const float*)d_in[13];
    const float* Wfr     = (const float*)d_in[14];
    const float* lnout_w = (const float*)d_in[15];
    const float* lnout_b = (const float*)d_in[16];
    const float* head_W  = (const float*)d_in[17];
    float* out = (float*)d_out;

    float *x, *r, *k, *v, *sa, *sb;
    float *aFkv, *aFk, *aBkv, *aBk, *iFkv, *iFk, *iBkv, *iBk;
    __nv_bfloat16 *wth, *wtl, *xnh, *xnl, *yh, *yl, *kfh, *kfl;
    cudaGetSymbolAddress((void**)&x,    g_x);
    cudaGetSymbolAddress((void**)&r,    g_r);
    cudaGetSymbolAddress((void**)&k,    g_k);
    cudaGetSymbolAddress((void**)&v,    g_v);
    cudaGetSymbolAddress((void**)&sa,   g_sakv);
    cudaGetSymbolAddress((void**)&sb,   g_sak);
    cudaGetSymbolAddress((void**)&wth,  g_wt_hi);
    cudaGetSymbolAddress((void**)&wtl,  g_wt_lo);
    cudaGetSymbolAddress((void**)&xnh,  g_xn_hi);
    cudaGetSymbolAddress((void**)&xnl,  g_xn_lo);
    cudaGetSymbolAddress((void**)&yh,   g_y_hi);
    cudaGetSymbolAddress((void**)&yl,   g_y_lo);
    cudaGetSymbolAddress((void**)&kfh,  g_kf_hi);
    cudaGetSymbolAddress((void**)&kfl,  g_kf_lo);
    cudaGetSymbolAddress((void**)&aFkv, g_aggFkv);
    cudaGetSymbolAddress((void**)&aFk,  g_aggFk);
    cudaGetSymbolAddress((void**)&aBkv, g_aggBkv);
    cudaGetSymbolAddress((void**)&aBk,  g_aggBk);
    cudaGetSymbolAddress((void**)&iFkv, g_iniFkv);
    cudaGetSymbolAddress((void**)&iFk,  g_iniFk);
    cudaGetSymbolAddress((void**)&iBkv, g_iniBkv);
    cudaGetSymbolAddress((void**)&iBk,  g_iniBk);

    cudaFuncSetAttribute(gemm_mma<0>, cudaFuncAttributeMaxDynamicSharedMemorySize, GEMM_SMEM);
    cudaFuncSetAttribute(gemm_mma<1>, cudaFuncAttributeMaxDynamicSharedMemorySize, GEMM_SMEM);
    cudaFuncSetAttribute(gemm_mma<2>, cudaFuncAttributeMaxDynamicSharedMemorySize, GEMM_SMEM);
    cudaFuncSetAttribute(gemm_mma<3>, cudaFuncAttributeMaxDynamicSharedMemorySize, GEMM_SMEM);
    cudaFuncSetAttribute(gemm_mma<4>, cudaFuncAttributeMaxDynamicSharedMemorySize, GEMM_SMEM);

    convert_all_k<<<4096, 256>>>((const float4*)Wr, (const float4*)Wk,
                                 (const float4*)Wv, (const float4*)Wo,
                                 (const float4*)Wfr, (const float4*)Wfk,
                                 (const float4*)Wfv, (const float4*)head_W,
                                 (uint2*)wth, (uint2*)wtl);

    embed_k<<<M, 256>>>(idx, emb, x);

    dim3 gCCg(M / 128, C / 128);   // 16 x 8
    dim3 gCFg(M / 128, F / 128);   // 16 x 32
    dim3 gCVg(M / 128, V / 128);   // 16 x 393

    for (int l = 0; l < L; l++) {
        size_t wcc = (size_t)l * C * C;
        size_t wcf = (size_t)l * C * F;
        const float* l1w = ln1_w + (size_t)l * C;
        const float* l1b = ln1_b + (size_t)l * C;
        const float* wd  = w_decay + (size_t)l * C;
        const float* ub  = u_bonus + (size_t)l * C;
        const float* l2w = ln2_w + (size_t)l * C;
        const float* l2b = ln2_b + (size_t)l * C;

        // time-mix
        layernorm_k<<<M, 256>>>(x, l1w, l1b, xnh, xnl);
        gemm_mma<1><<<gCCg, GTHREADS, GEMM_SMEM>>>(xnh, xnl, wth + O_WR + wcc, wtl + O_WR + wcc,
                                                   r, nullptr, nullptr, nullptr, nullptr, C, C);
        gemm_mma<0><<<gCCg, GTHREADS, GEMM_SMEM>>>(xnh, xnl, wth + O_WK + wcc, wtl + O_WK + wcc,
                                                   k, nullptr, nullptr, nullptr, nullptr, C, C);
        gemm_mma<0><<<gCCg, GTHREADS, GEMM_SMEM>>>(xnh, xnl, wth + O_WV + wcc, wtl + O_WV + wcc,
                                                   v, nullptr, nullptr, nullptr, nullptr, C, C);
        wkv_agg_k<<<(B * CH * C) / 256, 256>>>(k, v, wd, aFkv, aFk, aBkv, aBk);
        wkv_scan_k<<<(B * C) / 256, 256>>>(wd, aFkv, aFk, aBkv, aBk,
                                           iFkv, iFk, iBkv, iBk);
        wkv_apply_k<<<(B * CH * C) / 256, 256>>>(r, k, v, wd, ub,
                                                 iFkv, iFk, iBkv, iBk,
                                                 yh, yl, sa, sb);
        gemm_mma<3><<<gCCg, GTHREADS, GEMM_SMEM>>>(yh, yl, wth + O_WO + wcc, wtl + O_WO + wcc,
                                                   x, nullptr, nullptr, x, nullptr, C, C);

        // channel-mix
        layernorm_k<<<M, 256>>>(x, l2w, l2b, xnh, xnl);
        gemm_mma<1><<<gCCg, GTHREADS, GEMM_SMEM>>>(xnh, xnl, wth + O_WFR + wcc, wtl + O_WFR + wcc,
                                                   r, nullptr, nullptr, nullptr, nullptr, C, C);
        gemm_mma<2><<<gCFg, GTHREADS, GEMM_SMEM>>>(xnh, xnl, wth + O_WFK + wcf, wtl + O_WFK + wcf,
                                                   nullptr, kfh, kfl, nullptr, nullptr, F, C);
        gemm_mma<4><<<gCCg, GTHREADS, GEMM_SMEM>>>(kfh, kfl, wth + O_WFV + wcf, wtl + O_WFV + wcf,
                                                   x, nullptr, nullptr, x, r, C, F);
    }

    layernorm_k<<<M, 256>>>(x, lnout_w, lnout_b, xnh, xnl);
    gemm_mma<0><<<gCVg, GTHREADS, GEMM_SMEM>>>(xnh, xnl, wth + O_HEAD, wtl + O_HEAD,
                                               out, nullptr, nullptr, nullptr, nullptr, V, C);
}

// round 9
// speedup vs baseline: 1.1666x; 1.1530x over previous
#include <cuda_runtime.h>
#include <cuda_bf16.h>
#include <cstdint>
#include <math.h>

// ---------------------------------------------------------------------------
// Problem constants
// ---------------------------------------------------------------------------
constexpr int L = 4;
constexpr int C = 1024;
constexpr int F = 4096;
constexpr int V = 50304;
constexpr int B = 2;
constexpr int T = 1024;
constexpr int M = B * T;            // 2048 rows
constexpr int CH = 16;              // wkv chunks
constexpr int CL = 64;              // wkv chunk length

// ---------------------------------------------------------------------------
// Converted-weight layout: SAME [K,N] layout as inputs (no transpose).
// ---------------------------------------------------------------------------
constexpr size_t MB1 = size_t(C) * C;         // 1,048,576
constexpr size_t O_WR   = 0;                  // [L][C][C]  (Wk = +4MB1, Wv = +8MB1)
constexpr size_t O_WK   = 4 * MB1;
constexpr size_t O_WV   = 8 * MB1;
constexpr size_t O_WO   = 12 * MB1;
constexpr size_t O_WFR  = 16 * MB1;
constexpr size_t O_WFK  = 20 * MB1;           // [L][C][F]
constexpr size_t O_WFV  = 36 * MB1;           // [L][F][C]
constexpr size_t O_HEAD = 52 * MB1;           // [C][V]
constexpr size_t WTOTAL = O_HEAD + size_t(V) * C;

__device__ alignas(16) __nv_bfloat16 g_wt_hi[WTOTAL];
__device__ alignas(16) __nv_bfloat16 g_wt_lo[WTOTAL];

__device__ alignas(16) float g_x   [size_t(M) * C];
__device__ alignas(16) float g_r   [size_t(M) * C];
__device__ alignas(16) float g_k   [size_t(M) * C];
__device__ alignas(16) float g_v   [size_t(M) * C];
__device__ alignas(16) float g_sakv[size_t(M) * C];
__device__ alignas(16) float g_sak [size_t(M) * C];
__device__ alignas(16) __nv_bfloat16 g_xn_hi[size_t(M) * C];
__device__ alignas(16) __nv_bfloat16 g_xn_lo[size_t(M) * C];
__device__ alignas(16) __nv_bfloat16 g_y_hi [size_t(M) * C];
__device__ alignas(16) __nv_bfloat16 g_y_lo [size_t(M) * C];
__device__ alignas(16) __nv_bfloat16 g_kf_hi[size_t(M) * F];
__device__ alignas(16) __nv_bfloat16 g_kf_lo[size_t(M) * F];

// wkv chunk-scan scratch: [B][CH][C]
constexpr int AGG = B * CH * C;    // 32768
__device__ alignas(16) float g_aggFkv[AGG];
__device__ alignas(16) float g_aggFk [AGG];
__device__ alignas(16) float g_aggBkv[AGG];
__device__ alignas(16) float g_aggBk [AGG];
__device__ alignas(16) float g_iniFkv[AGG];
__device__ alignas(16) float g_iniFk [AGG];
__device__ alignas(16) float g_iniBkv[AGG];
__device__ alignas(16) float g_iniBk [AGG];

// ---------------------------------------------------------------------------
// Merged streaming split conversion: 16B stores (8 floats per thread-iter).
// ---------------------------------------------------------------------------
constexpr size_t N4_CC = size_t(L) * C * C / 4;
constexpr size_t N4_CF = size_t(L) * C * F / 4;
constexpr size_t N4_HD = size_t(V) * C / 4;
constexpr size_t CV_B0 = N4_CC;
constexpr size_t CV_B1 = CV_B0 + N4_CC;
constexpr size_t CV_B2 = CV_B1 + N4_CC;
constexpr size_t CV_B3 = CV_B2 + N4_CC;
constexpr size_t CV_B4 = CV_B3 + N4_CC;
constexpr size_t CV_B5 = CV_B4 + N4_CF;
constexpr size_t CV_B6 = CV_B5 + N4_CF;
constexpr size_t CV_TOT = CV_B6 + N4_HD;
constexpr size_t CV_G = CV_TOT / 2;           // groups of 2 float4 (8 floats)

__device__ __forceinline__ uint32_t pack_hi2(float a, float b) {
    __nv_bfloat162 h;
    h.x = __float2bfloat16(a);
    h.y = __float2bfloat16(b);
    return *(uint32_t*)&h;
}
__device__ __forceinline__ uint32_t pack_lo2(float a, float b, uint32_t hu) {
    __nv_bfloat162 h = *(__nv_bfloat162*)&hu;
    __nv_bfloat162 l;
    l.x = __float2bfloat16(a - __bfloat162float(h.x));
    l.y = __float2bfloat16(b - __bfloat162float(h.y));
    return *(uint32_t*)&l;
}

__global__ __launch_bounds__(256) void convert_all_k(
    const float4* __restrict__ wr, const float4* __restrict__ wk,
    const float4* __restrict__ wv, const float4* __restrict__ wo,
    const float4* __restrict__ wfr, const float4* __restrict__ wfk,
    const float4* __restrict__ wfv, const float4* __restrict__ hd,
    uint4* __restrict__ oh, uint4* __restrict__ ol) {
    size_t stride = (size_t)gridDim.x * blockDim.x;
    for (size_t g = (size_t)blockIdx.x * blockDim.x + threadIdx.x; g < CV_G;
         g += stride) {
        size_t i = 2 * g;
        const float4* src;
        size_t dstg;   // uint4 index
        if (i < CV_B0)      { src = wr  + i;            dstg = O_WR  / 8 + g; }
        else if (i < CV_B1) { src = wk  + (i - CV_B0);  dstg = O_WK  / 8 + (g - CV_B0 / 2); }
        else if (i < CV_B2) { src = wv  + (i - CV_B1);  dstg = O_WV  / 8 + (g - CV_B1 / 2); }
        else if (i < CV_B3) { src = wo  + (i - CV_B2);  dstg = O_WO  / 8 + (g - CV_B2 / 2); }
        else if (i < CV_B4) { src = wfr + (i - CV_B3);  dstg = O_WFR / 8 + (g - CV_B3 / 2); }
        else if (i < CV_B5) { src = wfk + (i - CV_B4);  dstg = O_WFK / 8 + (g - CV_B4 / 2); }
        else if (i < CV_B6) { src = wfv + (i - CV_B5);  dstg = O_WFV / 8 + (g - CV_B5 / 2); }
        else                { src = hd  + (i - CV_B6);  dstg = O_HEAD/ 8 + (g - CV_B6 / 2); }
        float4 w0 = src[0];
        float4 w1 = src[1];
        uint4 H, Lo;
        H.x = pack_hi2(w0.x, w0.y);  Lo.x = pack_lo2(w0.x, w0.y, H.x);
        H.y = pack_hi2(w0.z, w0.w);  Lo.y = pack_lo2(w0.z, w0.w, H.y);
        H.z = pack_hi2(w1.x, w1.y);  Lo.z = pack_lo2(w1.x, w1.y, H.z);
        H.w = pack_hi2(w1.z, w1.w);  Lo.w = pack_lo2(w1.z, w1.w, H.w);
        oh[dstg] = H;
        ol[dstg] = Lo;
    }
}

// ---------------------------------------------------------------------------
// Embedding gather
// ---------------------------------------------------------------------------
__global__ void embed_k(const int* __restrict__ idx,
                        const float* __restrict__ emb,
                        float* __restrict__ x) {
    int row = blockIdx.x;
    int id = idx[row];
    const float4* src = (const float4*)(emb + (size_t)id * C);
    float4* dst = (float4*)(x + (size_t)row * C);
    for (int i = threadIdx.x; i < C / 4; i += blockDim.x) dst[i] = src[i];
}

// ---------------------------------------------------------------------------
// LayerNorm -> split bf16 output
// ---------------------------------------------------------------------------
__global__ __launch_bounds__(256) void layernorm_k(const float* __restrict__ x,
                                                   const float* __restrict__ w,
                                                   const float* __restrict__ b,
                                                   __nv_bfloat16* __restrict__ out_hi,
                                                   __nv_bfloat16* __restrict__ out_lo) {
    __shared__ float red[256];
    int row = blockIdx.x;
    const float* xr = x + (size_t)row * C;
    float v[4];
    float s = 0.f;
#pragma unroll
    for (int i = 0; i < 4; i++) { v[i] = xr[threadIdx.x + 256 * i]; s += v[i]; }
    red[threadIdx.x] = s;
    __syncthreads();
    for (int o = 128; o > 0; o >>= 1) {
        if (threadIdx.x < o) red[threadIdx.x] += red[threadIdx.x + o];
        __syncthreads();
    }
    float mu = red[0] * (1.f / C);
    __syncthreads();
    float s2 = 0.f;
#pragma unroll
    for (int i = 0; i < 4; i++) { float d = v[i] - mu; s2 += d * d; }
    red[threadIdx.x] = s2;
    __syncthreads();
    for (int o = 128; o > 0; o >>= 1) {
        if (threadIdx.x < o) red[threadIdx.x] += red[threadIdx.x + o];
        __syncthreads();
    }
    float rstd = rsqrtf(red[0] * (1.f / C) + 1e-5f);
#pragma unroll
    for (int i = 0; i < 4; i++) {
        int c = threadIdx.x + 256 * i;
        float o = (v[i] - mu) * rstd * w[c] + b[c];
        __nv_bfloat16 h = __float2bfloat16(o);
        size_t off = (size_t)row * C + c;
        out_hi[off] = h;
        out_lo[off] = __float2bfloat16(o - __bfloat162float(h));
    }
}

// ---------------------------------------------------------------------------
// Split-bf16 tensor-core GEMM via mma.sync — round-6 proven core.
//   512 threads / 16 warps; CTA tile 128x128; BK=32; warp 4(m)x4(n) of 32x32.
//   3 MMA terms: Ah*Bh + Ah*Bl + Al*Bh (fp32 acc).  5-stage cp.async pipe.
// MODE 0 plain | 1 sigmoid | 2 relu^2->bf16 split | 3 res+acc | 4 res+gate*acc
// MODE 5 fused r/k/v  (blockIdx.y: 0-7 -> Wr/sigmoid->out0; 8-15 -> Wk->res;
//                      16-23 -> Wv->gate; weight blocks spaced 4*MB1)
// MODE 6 fused gate/kf (blockIdx.y: 0-7 -> Wfr(Bh)/sigmoid->out0 (N=C);
//                      8-39 -> Wfk(Bh2)/relu^2->outH,outL (N=F))
// ---------------------------------------------------------------------------
constexpr int BK = 32;
constexpr int SSTRA = 40;                     // A row pad (80B)
constexpr int SSTRB = 136;                    // B row pad (272B)
constexpr int TA = 128 * SSTRA * 2;           // 10240 B
constexpr int TB = BK * SSTRB * 2;            // 8704 B
constexpr int OFF_AH = 0;
constexpr int OFF_AL = TA;
constexpr int OFF_BH = 2 * TA;
constexpr int OFF_BL = 2 * TA + TB;
constexpr int STAGEB = 2 * TA + 2 * TB;       // 37888 B
constexpr int NSTAGE = 5;
constexpr int GEMM_SMEM = NSTAGE * STAGEB;    // 189440 B
constexpr int GTHREADS = 512;

__device__ __forceinline__ uint32_t smem_u32(const void* p) {
    uint32_t a;
    asm("{ .reg .u64 t; cvta.to.shared.u64 t, %1; cvt.u32.u64 %0, t; }"
        : "=r"(a) : "l"(p));
    return a;
}

__device__ __forceinline__ void ldsm_x4(uint32_t addr, uint32_t& r0, uint32_t& r1,
                                        uint32_t& r2, uint32_t& r3) {
    asm volatile("ldmatrix.sync.aligned.m8n8.x4.shared.b16 {%0,%1,%2,%3}, [%4];"
                 : "=r"(r0), "=r"(r1), "=r"(r2), "=r"(r3) : "r"(addr));
}

__device__ __forceinline__ void ldsm_x4_t(uint32_t addr, uint32_t& r0, uint32_t& r1,
                                          uint32_t& r2, uint32_t& r3) {
    asm volatile("ldmatrix.sync.aligned.m8n8.x4.trans.shared.b16 {%0,%1,%2,%3}, [%4];"
                 : "=r"(r0), "=r"(r1), "=r"(r2), "=r"(r3) : "r"(addr));
}

__device__ __forceinline__ void mma_bf16(float* d, const uint32_t* a,
                                         uint32_t b0, uint32_t b1) {
    asm volatile(
        "mma.sync.aligned.m16n8k16.row.col.f32.bf16.bf16.f32 "
        "{%0,%1,%2,%3}, {%4,%5,%6,%7}, {%8,%9}, {%0,%1,%2,%3};"
        : "+f"(d[0]), "+f"(d[1]), "+f"(d[2]), "+f"(d[3])
        : "r"(a[0]), "r"(a[1]), "r"(a[2]), "r"(a[3]), "r"(b0), "r"(b1));
}

__device__ __forceinline__ void cp16(uint32_t sp, const void* gp) {
    asm volatile("cp.async.cg.shared.global [%0], [%1], 16;" :: "r"(sp), "l"(gp));
}

// A tile: 128 rows x 32 k (64B/row). 128 threads: 1 row, 4 cp16 each.
__device__ __forceinline__ void issue_A(uint32_t dst, const __nv_bfloat16* __restrict__ g,
                                        int brow, int K, int k0, int t128) {
    int r = t128;
    const __nv_bfloat16* gp = g + (size_t)(brow + r) * K + k0;
    uint32_t sp = dst + r * (SSTRA * 2);
#pragma unroll
    for (int cc = 0; cc < 4; cc++)
        cp16(sp + cc * 16, gp + cc * 8);
}

// B tile: 32 k-rows x 128 n (256B/row = 16 chunks). 128 threads: 4 chunks each.
__device__ __forceinline__ void issue_B(uint32_t dst, const __nv_bfloat16* __restrict__ g,
                                        int bcol, int Nb, int k0, int t128) {
    int r = t128 >> 2;
    int c0 = (t128 & 3) * 4;
    const __nv_bfloat16* gp = g + (size_t)(k0 + r) * Nb + bcol + c0 * 8;
    uint32_t sp = dst + r * (SSTRB * 2) + c0 * 16;
#pragma unroll
    for (int cc = 0; cc < 4; cc++)
        cp16(sp + cc * 16, gp + cc * 8);
}

template <int MODE>
__global__ __launch_bounds__(GTHREADS, 1) void gemm_mma(
    const __nv_bfloat16* __restrict__ Ah, const __nv_bfloat16* __restrict__ Al,
    const __nv_bfloat16* __restrict__ Bh, const __nv_bfloat16* __restrict__ Bl,
    const __nv_bfloat16* __restrict__ Bh2, const __nv_bfloat16* __restrict__ Bl2,
    float* __restrict__ out0,
    __nv_bfloat16* __restrict__ outH, __nv_bfloat16* __restrict__ outL,
    const float* __restrict__ res, const float* __restrict__ gate,
    int N, int K) {
    extern __shared__ __align__(128) char sm[];
    uint32_t smem = smem_u32(sm);
    int tid = threadIdx.x;
    int wid = tid >> 5;
    int lane = tid & 31;
    int brow = blockIdx.x * 128;

    // ---- mode-dependent B selection / output routing ----
    int bcol, Nb, Nout, epi;
    const __nv_bfloat16 *BhS, *BlS;
    float* outp = out0;
    if (MODE == 5) {
        int sel = blockIdx.y >> 3;
        bcol = (blockIdx.y & 7) * 128;
        BhS = Bh + (size_t)sel * 4 * MB1;
        BlS = Bl + (size_t)sel * 4 * MB1;
        Nb = N; Nout = N;
        epi = (sel == 0) ? 1 : 0;
        outp = (sel == 0) ? out0 : (sel == 1 ? const_cast<float*>(res)
                                             : const_cast<float*>(gate));
    } else if (MODE == 6) {
        if (blockIdx.y < 8) {
            bcol = blockIdx.y * 128;
            BhS = Bh; BlS = Bl;
            Nb = C; Nout = C;
            epi = 1;
        } else {
            bcol = (blockIdx.y - 8) * 128;
            BhS = Bh2; BlS = Bl2;
            Nb = N; Nout = N;          // N = F
            epi = 2;
        }
    } else {
        bcol = blockIdx.y * 128;
        BhS = Bh; BlS = Bl;
        Nb = N; Nout = N;
        epi = MODE;
    }

    int warp_m = wid & 3;          // 0..3 (32 rows each)
    int warp_n = wid >> 2;         // 0..3 (32 cols each)
    int tile_id = tid >> 7;        // 0:Ah 1:Al 2:Bh 3:Bl
    int t128 = tid & 127;
    int ks_flip = (wid >> 2) & 1;  // stagger ks order across warp halves

    float acc[2][4][4];
#pragma unroll
    for (int i = 0; i < 2; i++)
#pragma unroll
        for (int j = 0; j < 4; j++)
#pragma unroll
            for (int q = 0; q < 4; q++) acc[i][j][q] = 0.f;

    int nch = K >> 5;              // BK = 32

    // prologue: stages 0..3
#pragma unroll
    for (int s = 0; s < NSTAGE - 1; s++) {
        uint32_t sb = smem + s * STAGEB;
        if (tile_id == 0)      issue_A(sb + OFF_AH, Ah, brow, K, s * BK, t128);
        else if (tile_id == 1) issue_A(sb + OFF_AL, Al, brow, K, s * BK, t128);
        else if (tile_id == 2) issue_B(sb + OFF_BH, BhS, bcol, Nb, s * BK, t128);
        else                   issue_B(sb + OFF_BL, BlS, bcol, Nb, s * BK, t128);
        asm volatile("cp.async.commit_group;");
    }

    int a_r = (lane & 15);
    int a_k = ((lane >> 4) << 3);
    int b_kr = (lane & 15);
    int b_nf = ((lane >> 4) << 3);

#pragma unroll 1
    for (int c = 0; c < nch; c++) {
        asm volatile("cp.async.wait_group 3;");   // NSTAGE-2
        __syncthreads();
        if (c + NSTAGE - 1 < nch) {
            uint32_t sb = smem + ((c + NSTAGE - 1) % NSTAGE) * STAGEB;
            int k0 = (c + NSTAGE - 1) * BK;
            if (tile_id == 0)      issue_A(sb + OFF_AH, Ah, brow, K, k0, t128);
            else if (tile_id == 1) issue_A(sb + OFF_AL, Al, brow, K, k0, t128);
            else if (tile_id == 2) issue_B(sb + OFF_BH, BhS, bcol, Nb, k0, t128);
            else                   issue_B(sb + OFF_BL, BlS, bcol, Nb, k0, t128);
        }
        asm volatile("cp.async.commit_group;");

        uint32_t sbase = smem + (c % NSTAGE) * STAGEB;
#pragma unroll
        for (int i2 = 0; i2 < 2; i2++) {
            int ks = ks_flip ? (1 - i2) : i2;   // warp-staggered order
            int kk = ks * 16;
            uint32_t ah[2][4], al[2][4], bh[4][2], bl[4][2];
            uint32_t acol = (uint32_t)(kk + a_k) * 2;
#pragma unroll
            for (int mi = 0; mi < 2; mi++) {
                uint32_t ad = sbase + OFF_AH +
                              (warp_m * 32 + mi * 16 + a_r) * (SSTRA * 2) + acol;
                ldsm_x4(ad, ah[mi][0], ah[mi][1], ah[mi][2], ah[mi][3]);
                ldsm_x4(ad + TA, al[mi][0], al[mi][1], al[mi][2], al[mi][3]);
            }
#pragma unroll
            for (int nj = 0; nj < 2; nj++) {
                uint32_t bd = sbase + OFF_BH + (kk + b_kr) * (SSTRB * 2) +
                              (warp_n * 32 + nj * 16 + b_nf) * 2;
                uint32_t r0, r1, r2, r3;
                ldsm_x4_t(bd, r0, r1, r2, r3);
                bh[nj * 2][0] = r0;     bh[nj * 2][1] = r1;
                bh[nj * 2 + 1][0] = r2; bh[nj * 2 + 1][1] = r3;
                ldsm_x4_t(bd + TB, r0, r1, r2, r3);
                bl[nj * 2][0] = r0;     bl[nj * 2][1] = r1;
                bl[nj * 2 + 1][0] = r2; bl[nj * 2 + 1][1] = r3;
            }
#pragma unroll
            for (int mi = 0; mi < 2; mi++)
#pragma unroll
                for (int ni = 0; ni < 4; ni++)
                    mma_bf16(acc[mi][ni], ah[mi], bh[ni][0], bh[ni][1]);
#pragma unroll
            for (int mi = 0; mi < 2; mi++)
#pragma unroll
                for (int ni = 0; ni < 4; ni++)
                    mma_bf16(acc[mi][ni], ah[mi], bl[ni][0], bl[ni][1]);
#pragma unroll
            for (int mi = 0; mi < 2; mi++)
#pragma unroll
                for (int ni = 0; ni < 4; ni++)
                    mma_bf16(acc[mi][ni], al[mi], bh[ni][0], bh[ni][1]);
        }
    }

    // ---- epilogue ----
    int qrow = lane >> 2;
    int qcol = (lane & 3) * 2;
#pragma unroll
    for (int mi = 0; mi < 2; mi++) {
#pragma unroll
        for (int h = 0; h < 2; h++) {
            int row = brow + warp_m * 32 + mi * 16 + qrow + h * 8;
#pragma unroll
            for (int ni = 0; ni < 4; ni++) {
                int col = bcol + warp_n * 32 + ni * 8 + qcol;
                size_t off = (size_t)row * Nout + col;
                float o0 = acc[mi][ni][h * 2];
                float o1 = acc[mi][ni][h * 2 + 1];
                if (MODE == 3) {
                    const float2 rv = *(const float2*)(res + off);
                    o0 += rv.x; o1 += rv.y;
                } else if (MODE == 4) {
                    const float2 rv = *(const float2*)(res + off);
                    const float2 gv = *(const float2*)(gate + off);
                    o0 = rv.x + gv.x * o0;
                    o1 = rv.y + gv.y * o1;
                } else if (epi == 1) {
                    o0 = 1.f / (1.f + expf(-o0));
                    o1 = 1.f / (1.f + expf(-o1));
                }
                if (epi == 2) {
                    o0 = fmaxf(o0, 0.f); o0 *= o0;
                    o1 = fmaxf(o1, 0.f); o1 *= o1;
                    __nv_bfloat16 h0 = __float2bfloat16(o0);
                    __nv_bfloat16 h1 = __float2bfloat16(o1);
                    __nv_bfloat162 hp; hp.x = h0; hp.y = h1;
                    __nv_bfloat162 lp;
                    lp.x = __float2bfloat16(o0 - __bfloat162float(h0));
                    lp.y = __float2bfloat16(o1 - __bfloat162float(h1));
                    *(__nv_bfloat162*)(outH + off) = hp;
                    *(__nv_bfloat162*)(outL + off) = lp;
                } else {
                    float2 ov = make_float2(o0, o1);
                    *(float2*)(outp + off) = ov;
                }
            }
        }
    }
}

// ---------------------------------------------------------------------------
// Chunk-parallel bidirectional WKV (3 kernels).
// ---------------------------------------------------------------------------
__global__ __launch_bounds__(256) void wkv_agg_k(
    const float* __restrict__ k, const float* __restrict__ v,
    const float* __restrict__ w,
    float* __restrict__ aFkv, float* __restrict__ aFk,
    float* __restrict__ aBkv, float* __restrict__ aBk) {
    int gid = blockIdx.x * blockDim.x + threadIdx.x;
    int c = gid & (C - 1);
    int ch = (gid >> 10) & (CH - 1);
    int b = gid >> 14;
    float d = expf(-expf(w[c]));
    size_t base = (size_t)b * T * C + (size_t)ch * CL * C + c;

    float fkv = 0.f, fk = 0.f, bkv = 0.f, bk = 0.f, pw = 1.f;
#pragma unroll 4
    for (int i = 0; i < CL; i++) {
        size_t o = base + (size_t)i * C;
        float ek = expf(k[o]);
        float kv = ek * v[o];
        fkv = fkv * d + kv;
        fk  = fk  * d + ek;
        bkv += kv * pw;
        bk  += ek * pw;
        pw *= d;
    }
    aFkv[gid] = fkv; aFk[gid] = fk;
    aBkv[gid] = bkv; aBk[gid] = bk;
}

__global__ __launch_bounds__(256) void wkv_scan_k(
    const float* __restrict__ w,
    const float* __restrict__ aFkv, const float* __restrict__ aFk,
    const float* __restrict__ aBkv, const float* __restrict__ aBk,
    float* __restrict__ iFkv, float* __restrict__ iFk,
    float* __restrict__ iBkv, float* __restrict__ iBk) {
    int gid = blockIdx.x * blockDim.x + threadIdx.x;
    int c = gid & (C - 1);
    int b = gid >> 10;
    float D = expf(-(float)CL * expf(w[c]));
    int base = b * CH * C + c;

    float skv = 0.f, sk = 0.f;
#pragma unroll
    for (int ch = 0; ch < CH; ch++) {
        int ai = base + ch * C;
        iFkv[ai] = skv; iFk[ai] = sk;
        skv = skv * D + aFkv[ai];
        sk  = sk  * D + aFk[ai];
    }
    skv = 0.f; sk = 0.f;
#pragma unroll
    for (int ch = CH - 1; ch >= 0; ch--) {
        int ai = base + ch * C;
        iBkv[ai] = skv; iBk[ai] = sk;
        skv = skv * D + aBkv[ai];
        sk  = sk  * D + aBk[ai];
    }
}

__global__ __launch_bounds__(256) void wkv_apply_k(
    const float* __restrict__ r, const float* __restrict__ k,
    const float* __restrict__ v, const float* __restrict__ w,
    const float* __restrict__ u,
    const float* __restrict__ iFkv, const float* __restrict__ iFk,
    const float* __restrict__ iBkv, const float* __restrict__ iBk,
    __nv_bfloat16* __restrict__ y_hi, __nv_bfloat16* __restrict__ y_lo,
    float* __restrict__ sakv, float* __restrict__ sak) {
    int gid = blockIdx.x * blockDim.x + threadIdx.x;
    int c = gid & (C - 1);
    int ch = (gid >> 10) & (CH - 1);
    int b = gid >> 14;
    float d = expf(-expf(w[c]));
    float eu = expf(u[c]);
    size_t base = (size_t)b * T * C + (size_t)ch * CL * C + c;

    float fkv = iFkv[gid], fk = iFk[gid];
#pragma unroll 4
    for (int i = 0; i < CL; i++) {
        size_t o = base + (size_t)i * C;
        float ek = expf(k[o]);
        float kv = ek * v[o];
        sakv[o] = fkv;
        sak[o]  = fk;
        fkv = fkv * d + kv;
        fk  = fk  * d + ek;
    }
    float bkv = iBkv[gid], bk = iBk[gid];
#pragma unroll 4
    for (int i = CL - 1; i >= 0; i--) {
        size_t o = base + (size_t)i * C;
        float vv = v[o];
        float ek = expf(k[o]);
        float kv = ek * vv;
        float num = sakv[o] + bkv + eu * vv;
        float den = sak[o]  + bk  + eu;
        float yv = r[o] * num / (den + 1e-8f);
        __nv_bfloat16 h = __float2bfloat16(yv);
        y_hi[o] = h;
        y_lo[o] = __float2bfloat16(yv - __bfloat162float(h));
        bkv = bkv * d + kv;
        bk  = bk  * d + ek;
    }
}

// ---------------------------------------------------------------------------
// Host launch
// ---------------------------------------------------------------------------
extern "C" void kernel_launch(void* const* d_in, const int* in_sizes, int n_in,
                              void* d_out, int out_size) {
    const int*   idx     = (const int*)  d_in[0];
    const float* emb     = (const float*)d_in[1];
    const float* ln1_w   = (const float*)d_in[2];
    const float* ln1_b   = (const float*)d_in[3];
    const float* Wr      = (const float*)d_in[4];
    const float* Wk      = (const float*)d_in[5];
    const float* Wv      = (const float*)d_in[6];
    const float* w_decay = (const float*)d_in[7];
    const float* u_bonus = (const float*)d_in[8];
    const float* Wo      = (const float*)d_in[9];
    const float* ln2_w   = (const float*)d_in[10];
    const float* ln2_b   = (const float*)d_in[11];
    const float* Wfk     = (const float*)d_in[12];
    const float* Wfv     = (const float*)d_in[13];
    const float* Wfr     = (const float*)d_in[14];
    const float* lnout_w = (const float*)d_in[15];
    const float* lnout_b = (const float*)d_in[16];
    const float* head_W  = (const float*)d_in[17];
    float* out = (float*)d_out;

    float *x, *r, *k, *v, *sa, *sb;
    float *aFkv, *aFk, *aBkv, *aBk, *iFkv, *iFk, *iBkv, *iBk;
    __nv_bfloat16 *wth, *wtl, *xnh, *xnl, *yh, *yl, *kfh, *kfl;
    cudaGetSymbolAddress((void**)&x,    g_x);
    cudaGetSymbolAddress((void**)&r,    g_r);
    cudaGetSymbolAddress((void**)&k,    g_k);
    cudaGetSymbolAddress((void**)&v,    g_v);
    cudaGetSymbolAddress((void**)&sa,   g_sakv);
    cudaGetSymbolAddress((void**)&sb,   g_sak);
    cudaGetSymbolAddress((void**)&wth,  g_wt_hi);
    cudaGetSymbolAddress((void**)&wtl,  g_wt_lo);
    cudaGetSymbolAddress((void**)&xnh,  g_xn_hi);
    cudaGetSymbolAddress((void**)&xnl,  g_xn_lo);
    cudaGetSymbolAddress((void**)&yh,   g_y_hi);
    cudaGetSymbolAddress((void**)&yl,   g_y_lo);
    cudaGetSymbolAddress((void**)&kfh,  g_kf_hi);
    cudaGetSymbolAddress((void**)&kfl,  g_kf_lo);
    cudaGetSymbolAddress((void**)&aFkv, g_aggFkv);
    cudaGetSymbolAddress((void**)&aFk,  g_aggFk);
    cudaGetSymbolAddress((void**)&aBkv, g_aggBkv);
    cudaGetSymbolAddress((void**)&aBk,  g_aggBk);
    cudaGetSymbolAddress((void**)&iFkv, g_iniFkv);
    cudaGetSymbolAddress((void**)&iFk,  g_iniFk);
    cudaGetSymbolAddress((void**)&iBkv, g_iniBkv);
    cudaGetSymbolAddress((void**)&iBk,  g_iniBk);

    cudaFuncSetAttribute(gemm_mma<0>, cudaFuncAttributeMaxDynamicSharedMemorySize, GEMM_SMEM);
    cudaFuncSetAttribute(gemm_mma<3>, cudaFuncAttributeMaxDynamicSharedMemorySize, GEMM_SMEM);
    cudaFuncSetAttribute(gemm_mma<4>, cudaFuncAttributeMaxDynamicSharedMemorySize, GEMM_SMEM);
    cudaFuncSetAttribute(gemm_mma<5>, cudaFuncAttributeMaxDynamicSharedMemorySize, GEMM_SMEM);
    cudaFuncSetAttribute(gemm_mma<6>, cudaFuncAttributeMaxDynamicSharedMemorySize, GEMM_SMEM);

    convert_all_k<<<4096, 256>>>((const float4*)Wr, (const float4*)Wk,
                                 (const float4*)Wv, (const float4*)Wo,
                                 (const float4*)Wfr, (const float4*)Wfk,
                                 (const float4*)Wfv, (const float4*)head_W,
                                 (uint4*)wth, (uint4*)wtl);

    embed_k<<<M, 256>>>(idx, emb, x);

    dim3 gRKV(M / 128, 24);        // fused r/k/v     (384 CTAs)
    dim3 gCM (M / 128, 40);        // fused gate/kf   (640 CTAs)
    dim3 gCCg(M / 128, C / 128);   // 16 x 8
    dim3 gCVg(M / 128, V / 128);   // 16 x 393

    for (int l = 0; l < L; l++) {
        size_t wcc = (size_t)l * C * C;
        size_t wcf = (size_t)l * C * F;
        const float* l1w = ln1_w + (size_t)l * C;
        const float* l1b = ln1_b + (size_t)l * C;
        const float* wd  = w_decay + (size_t)l * C;
        const float* ub  = u_bonus + (size_t)l * C;
        const float* l2w = ln2_w + (size_t)l * C;
        const float* l2b = ln2_b + (size_t)l * C;

        // time-mix
        layernorm_k<<<M, 256>>>(x, l1w, l1b, xnh, xnl);
        // fused r/k/v: out0=r(sigmoid), res=k, gate=v
        gemm_mma<5><<<gRKV, GTHREADS, GEMM_SMEM>>>(
            xnh, xnl, wth + O_WR + wcc, wtl + O_WR + wcc, nullptr, nullptr,
            r, nullptr, nullptr, k, v, C, C);
        wkv_agg_k<<<(B * CH * C) / 256, 256>>>(k, v, wd, aFkv, aFk, aBkv, aBk);
        wkv_scan_k<<<(B * C) / 256, 256>>>(wd, aFkv, aFk, aBkv, aBk,
                                           iFkv, iFk, iBkv, iBk);
        wkv_apply_k<<<(B * CH * C) / 256, 256>>>(r, k, v, wd, ub,
                                                 iFkv, iFk, iBkv, iBk,
                                                 yh, yl, sa, sb);
        gemm_mma<3><<<gCCg, GTHREADS, GEMM_SMEM>>>(
            yh, yl, wth + O_WO + wcc, wtl + O_WO + wcc, nullptr, nullptr,
            x, nullptr, nullptr, x, nullptr, C, C);

        // channel-mix
        layernorm_k<<<M, 256>>>(x, l2w, l2b, xnh, xnl);
        // fused gate/kf: Bh=Wfr (N=C, sigmoid->r), Bh2=Wfk (N=F, relu^2->kf)
        gemm_mma<6><<<gCM, GTHREADS, GEMM_SMEM>>>(
            xnh, xnl, wth + O_WFR + wcc, wtl + O_WFR + wcc,
            wth + O_WFK + wcf, wtl + O_WFK + wcf,
            r, kfh, kfl, nullptr, nullptr, F, C);
        gemm_mma<4><<<gCCg, GTHREADS, GEMM_SMEM>>>(
            kfh, kfl, wth + O_WFV + wcf, wtl + O_WFV + wcf, nullptr, nullptr,
            x, nullptr, nullptr, x, r, C, F);
    }

    layernorm_k<<<M, 256>>>(x, lnout_w, lnout_b, xnh, xnl);
    gemm_mma<0><<<gCVg, GTHREADS, GEMM_SMEM>>>(
        xnh, xnl, wth + O_HEAD, wtl + O_HEAD, nullptr, nullptr,
        out, nullptr, nullptr, nullptr, nullptr, V, C);
}

// round 10
// speedup vs baseline: 1.2027x; 1.0310x over previous
#include <cuda_runtime.h>
#include <cuda_bf16.h>
#include <cstdint>
#include <math.h>

// ---------------------------------------------------------------------------
// Problem constants
// ---------------------------------------------------------------------------
constexpr int L = 4;
constexpr int C = 1024;
constexpr int F = 4096;
constexpr int V = 50304;
constexpr int B = 2;
constexpr int T = 1024;
constexpr int M = B * T;            // 2048 rows
constexpr int CH = 16;              // wkv chunks
constexpr int CL = 64;              // wkv chunk length

// ---------------------------------------------------------------------------
// Converted-weight layout: SAME [K,N] layout as inputs (no transpose).
// ---------------------------------------------------------------------------
constexpr size_t MB1 = size_t(C) * C;         // 1,048,576
constexpr size_t O_WR   = 0;                  // [L][C][C]  (Wk = +4MB1, Wv = +8MB1)
constexpr size_t O_WK   = 4 * MB1;
constexpr size_t O_WV   = 8 * MB1;
constexpr size_t O_WO   = 12 * MB1;
constexpr size_t O_WFR  = 16 * MB1;
constexpr size_t O_WFK  = 20 * MB1;           // [L][C][F]
constexpr size_t O_WFV  = 36 * MB1;           // [L][F][C]
constexpr size_t O_HEAD = 52 * MB1;           // [C][V]
constexpr size_t WTOTAL = O_HEAD + size_t(V) * C;

__device__ alignas(16) __nv_bfloat16 g_wt_hi[WTOTAL];
__device__ alignas(16) __nv_bfloat16 g_wt_lo[WTOTAL];

__device__ alignas(16) float g_x   [size_t(M) * C];
__device__ alignas(16) float g_r   [size_t(M) * C];
__device__ alignas(16) float g_k   [size_t(M) * C];
__device__ alignas(16) float g_v   [size_t(M) * C];
__device__ alignas(16) float g_sakv[size_t(M) * C];
__device__ alignas(16) float g_sak [size_t(M) * C];
__device__ alignas(16) __nv_bfloat16 g_xn_hi[size_t(M) * C];
__device__ alignas(16) __nv_bfloat16 g_xn_lo[size_t(M) * C];
__device__ alignas(16) __nv_bfloat16 g_y_hi [size_t(M) * C];
__device__ alignas(16) __nv_bfloat16 g_y_lo [size_t(M) * C];
__device__ alignas(16) __nv_bfloat16 g_kf_hi[size_t(M) * F];
__device__ alignas(16) __nv_bfloat16 g_kf_lo[size_t(M) * F];

// wkv chunk-scan scratch: [B][CH][C]
constexpr int AGG = B * CH * C;    // 32768
__device__ alignas(16) float g_aggFkv[AGG];
__device__ alignas(16) float g_aggFk [AGG];
__device__ alignas(16) float g_aggBkv[AGG];
__device__ alignas(16) float g_aggBk [AGG];
__device__ alignas(16) float g_iniFkv[AGG];
__device__ alignas(16) float g_iniFk [AGG];
__device__ alignas(16) float g_iniBkv[AGG];
__device__ alignas(16) float g_iniBk [AGG];

// ---------------------------------------------------------------------------
// Merged streaming split conversion: 16B stores (8 floats per thread-iter).
// ---------------------------------------------------------------------------
constexpr size_t N4_CC = size_t(L) * C * C / 4;
constexpr size_t N4_CF = size_t(L) * C * F / 4;
constexpr size_t N4_HD = size_t(V) * C / 4;
constexpr size_t CV_B0 = N4_CC;
constexpr size_t CV_B1 = CV_B0 + N4_CC;
constexpr size_t CV_B2 = CV_B1 + N4_CC;
constexpr size_t CV_B3 = CV_B2 + N4_CC;
constexpr size_t CV_B4 = CV_B3 + N4_CC;
constexpr size_t CV_B5 = CV_B4 + N4_CF;
constexpr size_t CV_B6 = CV_B5 + N4_CF;
constexpr size_t CV_TOT = CV_B6 + N4_HD;
constexpr size_t CV_G = CV_TOT / 2;           // groups of 2 float4 (8 floats)

__device__ __forceinline__ uint32_t pack_hi2(float a, float b) {
    __nv_bfloat162 h;
    h.x = __float2bfloat16(a);
    h.y = __float2bfloat16(b);
    return *(uint32_t*)&h;
}
__device__ __forceinline__ uint32_t pack_lo2(float a, float b, uint32_t hu) {
    __nv_bfloat162 h = *(__nv_bfloat162*)&hu;
    __nv_bfloat162 l;
    l.x = __float2bfloat16(a - __bfloat162float(h.x));
    l.y = __float2bfloat16(b - __bfloat162float(h.y));
    return *(uint32_t*)&l;
}

__global__ __launch_bounds__(256) void convert_all_k(
    const float4* __restrict__ wr, const float4* __restrict__ wk,
    const float4* __restrict__ wv, const float4* __restrict__ wo,
    const float4* __restrict__ wfr, const float4* __restrict__ wfk,
    const float4* __restrict__ wfv, const float4* __restrict__ hd,
    uint4* __restrict__ oh, uint4* __restrict__ ol) {
    size_t stride = (size_t)gridDim.x * blockDim.x;
    for (size_t g = (size_t)blockIdx.x * blockDim.x + threadIdx.x; g < CV_G;
         g += stride) {
        size_t i = 2 * g;
        const float4* src;
        size_t dstg;   // uint4 index
        if (i < CV_B0)      { src = wr  + i;            dstg = O_WR  / 8 + g; }
        else if (i < CV_B1) { src = wk  + (i - CV_B0);  dstg = O_WK  / 8 + (g - CV_B0 / 2); }
        else if (i < CV_B2) { src = wv  + (i - CV_B1);  dstg = O_WV  / 8 + (g - CV_B1 / 2); }
        else if (i < CV_B3) { src = wo  + (i - CV_B2);  dstg = O_WO  / 8 + (g - CV_B2 / 2); }
        else if (i < CV_B4) { src = wfr + (i - CV_B3);  dstg = O_WFR / 8 + (g - CV_B3 / 2); }
        else if (i < CV_B5) { src = wfk + (i - CV_B4);  dstg = O_WFK / 8 + (g - CV_B4 / 2); }
        else if (i < CV_B6) { src = wfv + (i - CV_B5);  dstg = O_WFV / 8 + (g - CV_B5 / 2); }
        else                { src = hd  + (i - CV_B6);  dstg = O_HEAD/ 8 + (g - CV_B6 / 2); }
        float4 w0 = src[0];
        float4 w1 = src[1];
        uint4 H, Lo;
        H.x = pack_hi2(w0.x, w0.y);  Lo.x = pack_lo2(w0.x, w0.y, H.x);
        H.y = pack_hi2(w0.z, w0.w);  Lo.y = pack_lo2(w0.z, w0.w, H.y);
        H.z = pack_hi2(w1.x, w1.y);  Lo.z = pack_lo2(w1.x, w1.y, H.z);
        H.w = pack_hi2(w1.z, w1.w);  Lo.w = pack_lo2(w1.z, w1.w, H.w);
        oh[dstg] = H;
        ol[dstg] = Lo;
    }
}

// ---------------------------------------------------------------------------
// Embedding gather
// ---------------------------------------------------------------------------
__global__ void embed_k(const int* __restrict__ idx,
                        const float* __restrict__ emb,
                        float* __restrict__ x) {
    int row = blockIdx.x;
    int id = idx[row];
    const float4* src = (const float4*)(emb + (size_t)id * C);
    float4* dst = (float4*)(x + (size_t)row * C);
    for (int i = threadIdx.x; i < C / 4; i += blockDim.x) dst[i] = src[i];
}

// ---------------------------------------------------------------------------
// LayerNorm -> split bf16 output
// ---------------------------------------------------------------------------
__global__ __launch_bounds__(256) void layernorm_k(const float* __restrict__ x,
                                                   const float* __restrict__ w,
                                                   const float* __restrict__ b,
                                                   __nv_bfloat16* __restrict__ out_hi,
                                                   __nv_bfloat16* __restrict__ out_lo) {
    __shared__ float red[256];
    int row = blockIdx.x;
    const float* xr = x + (size_t)row * C;
    float v[4];
    float s = 0.f;
#pragma unroll
    for (int i = 0; i < 4; i++) { v[i] = xr[threadIdx.x + 256 * i]; s += v[i]; }
    red[threadIdx.x] = s;
    __syncthreads();
    for (int o = 128; o > 0; o >>= 1) {
        if (threadIdx.x < o) red[threadIdx.x] += red[threadIdx.x + o];
        __syncthreads();
    }
    float mu = red[0] * (1.f / C);
    __syncthreads();
    float s2 = 0.f;
#pragma unroll
    for (int i = 0; i < 4; i++) { float d = v[i] - mu; s2 += d * d; }
    red[threadIdx.x] = s2;
    __syncthreads();
    for (int o = 128; o > 0; o >>= 1) {
        if (threadIdx.x < o) red[threadIdx.x] += red[threadIdx.x + o];
        __syncthreads();
    }
    float rstd = rsqrtf(red[0] * (1.f / C) + 1e-5f);
#pragma unroll
    for (int i = 0; i < 4; i++) {
        int c = threadIdx.x + 256 * i;
        float o = (v[i] - mu) * rstd * w[c] + b[c];
        __nv_bfloat16 h = __float2bfloat16(o);
        size_t off = (size_t)row * C + c;
        out_hi[off] = h;
        out_lo[off] = __float2bfloat16(o - __bfloat162float(h));
    }
}

// ---------------------------------------------------------------------------
// Split-bf16 tensor-core GEMM via mma.sync — pipelined instruction stream.
//   512 threads / 16 warps; CTA tile 128x128; BK=32; warp 4(m)x4(n) of 32x32.
//   3 MMA terms: Ah*Bh + Ah*Bl + Al*Bh (fp32 acc).  5-stage cp.async pipe.
//   Per-chunk stream per warp (volatile asm = strict issue order):
//     LDSM(hi) -> MMA hh -> LDSM(lo) -> [cp.async c+4 on ks0] -> MMA hl, lh
// MODE 0 plain | 3 res+acc | 4 res+gate*acc
// MODE 5 fused r/k/v   | MODE 6 fused gate(N=C)/kf(N=F)
// ---------------------------------------------------------------------------
constexpr int BK = 32;
constexpr int SSTRA = 40;                     // A row pad (80B)
constexpr int SSTRB = 136;                    // B row pad (272B)
constexpr int TA = 128 * SSTRA * 2;           // 10240 B
constexpr int TB = BK * SSTRB * 2;            // 8704 B
constexpr int OFF_AH = 0;
constexpr int OFF_AL = TA;
constexpr int OFF_BH = 2 * TA;
constexpr int OFF_BL = 2 * TA + TB;
constexpr int STAGEB = 2 * TA + 2 * TB;       // 37888 B
constexpr int NSTAGE = 5;
constexpr int GEMM_SMEM = NSTAGE * STAGEB;    // 189440 B
constexpr int GTHREADS = 512;

__device__ __forceinline__ uint32_t smem_u32(const void* p) {
    uint32_t a;
    asm("{ .reg .u64 t; cvta.to.shared.u64 t, %1; cvt.u32.u64 %0, t; }"
        : "=r"(a) : "l"(p));
    return a;
}

__device__ __forceinline__ void ldsm_x4(uint32_t addr, uint32_t& r0, uint32_t& r1,
                                        uint32_t& r2, uint32_t& r3) {
    asm volatile("ldmatrix.sync.aligned.m8n8.x4.shared.b16 {%0,%1,%2,%3}, [%4];"
                 : "=r"(r0), "=r"(r1), "=r"(r2), "=r"(r3) : "r"(addr));
}

__device__ __forceinline__ void ldsm_x4_t(uint32_t addr, uint32_t& r0, uint32_t& r1,
                                          uint32_t& r2, uint32_t& r3) {
    asm volatile("ldmatrix.sync.aligned.m8n8.x4.trans.shared.b16 {%0,%1,%2,%3}, [%4];"
                 : "=r"(r0), "=r"(r1), "=r"(r2), "=r"(r3) : "r"(addr));
}

__device__ __forceinline__ void mma_bf16(float* d, const uint32_t* a,
                                         uint32_t b0, uint32_t b1) {
    asm volatile(
        "mma.sync.aligned.m16n8k16.row.col.f32.bf16.bf16.f32 "
        "{%0,%1,%2,%3}, {%4,%5,%6,%7}, {%8,%9}, {%0,%1,%2,%3};"
        : "+f"(d[0]), "+f"(d[1]), "+f"(d[2]), "+f"(d[3])
        : "r"(a[0]), "r"(a[1]), "r"(a[2]), "r"(a[3]), "r"(b0), "r"(b1));
}

__device__ __forceinline__ void cp16(uint32_t sp, const void* gp) {
    asm volatile("cp.async.cg.shared.global [%0], [%1], 16;" :: "r"(sp), "l"(gp));
}

// A tile: 128 rows x 32 k (64B/row). 128 threads: 1 row, 4 cp16 each.
__device__ __forceinline__ void issue_A(uint32_t dst, const __nv_bfloat16* __restrict__ g,
                                        int brow, int K, int k0, int t128) {
    int r = t128;
    const __nv_bfloat16* gp = g + (size_t)(brow + r) * K + k0;
    uint32_t sp = dst + r * (SSTRA * 2);
#pragma unroll
    for (int cc = 0; cc < 4; cc++)
        cp16(sp + cc * 16, gp + cc * 8);
}

// B tile: 32 k-rows x 128 n (256B/row = 16 chunks). 128 threads: 4 chunks each.
__device__ __forceinline__ void issue_B(uint32_t dst, const __nv_bfloat16* __restrict__ g,
                                        int bcol, int Nb, int k0, int t128) {
    int r = t128 >> 2;
    int c0 = (t128 & 3) * 4;
    const __nv_bfloat16* gp = g + (size_t)(k0 + r) * Nb + bcol + c0 * 8;
    uint32_t sp = dst + r * (SSTRB * 2) + c0 * 16;
#pragma unroll
    for (int cc = 0; cc < 4; cc++)
        cp16(sp + cc * 16, gp + cc * 8);
}

template <int MODE>
__global__ __launch_bounds__(GTHREADS, 1) void gemm_mma(
    const __nv_bfloat16* __restrict__ Ah, const __nv_bfloat16* __restrict__ Al,
    const __nv_bfloat16* __restrict__ Bh, const __nv_bfloat16* __restrict__ Bl,
    const __nv_bfloat16* __restrict__ Bh2, const __nv_bfloat16* __restrict__ Bl2,
    float* __restrict__ out0,
    __nv_bfloat16* __restrict__ outH, __nv_bfloat16* __restrict__ outL,
    const float* __restrict__ res, const float* __restrict__ gate,
    int N, int K) {
    extern __shared__ __align__(128) char sm[];
    uint32_t smem = smem_u32(sm);
    int tid = threadIdx.x;
    int wid = tid >> 5;
    int lane = tid & 31;
    int brow = blockIdx.x * 128;

    // ---- mode-dependent B selection / output routing ----
    int bcol, Nb, Nout, epi;
    const __nv_bfloat16 *BhS, *BlS;
    float* outp = out0;
    if (MODE == 5) {
        int sel = blockIdx.y >> 3;
        bcol = (blockIdx.y & 7) * 128;
        BhS = Bh + (size_t)sel * 4 * MB1;
        BlS = Bl + (size_t)sel * 4 * MB1;
        Nb = N; Nout = N;
        epi = (sel == 0) ? 1 : 0;
        outp = (sel == 0) ? out0 : (sel == 1 ? const_cast<float*>(res)
                                             : const_cast<float*>(gate));
    } else if (MODE == 6) {
        if (blockIdx.y < 8) {
            bcol = blockIdx.y * 128;
            BhS = Bh; BlS = Bl;
            Nb = C; Nout = C;
            epi = 1;
        } else {
            bcol = (blockIdx.y - 8) * 128;
            BhS = Bh2; BlS = Bl2;
            Nb = N; Nout = N;          // N = F
            epi = 2;
        }
    } else {
        bcol = blockIdx.y * 128;
        BhS = Bh; BlS = Bl;
        Nb = N; Nout = N;
        epi = MODE;
    }

    int warp_m = wid & 3;          // 0..3 (32 rows each)
    int warp_n = wid >> 2;         // 0..3 (32 cols each)
    int tile_id = tid >> 7;        // 0:Ah 1:Al 2:Bh 3:Bl
    int t128 = tid & 127;

    float acc[2][4][4];
#pragma unroll
    for (int i = 0; i < 2; i++)
#pragma unroll
        for (int j = 0; j < 4; j++)
#pragma unroll
            for (int q = 0; q < 4; q++) acc[i][j][q] = 0.f;

    int nch = K >> 5;              // BK = 32

    // prologue: stages 0..3
#pragma unroll
    for (int s = 0; s < NSTAGE - 1; s++) {
        uint32_t sb = smem + s * STAGEB;
        if (tile_id == 0)      issue_A(sb + OFF_AH, Ah, brow, K, s * BK, t128);
        else if (tile_id == 1) issue_A(sb + OFF_AL, Al, brow, K, s * BK, t128);
        else if (tile_id == 2) issue_B(sb + OFF_BH, BhS, bcol, Nb, s * BK, t128);
        else                   issue_B(sb + OFF_BL, BlS, bcol, Nb, s * BK, t128);
        asm volatile("cp.async.commit_group;");
    }

    int a_r = (lane & 15);
    int a_k = ((lane >> 4) << 3);
    int b_kr = (lane & 15);
    int b_nf = ((lane >> 4) << 3);

#pragma unroll 1
    for (int c = 0; c < nch; c++) {
        asm volatile("cp.async.wait_group 3;");   // NSTAGE-2
        __syncthreads();
        uint32_t sbase = smem + (c % NSTAGE) * STAGEB;

#pragma unroll
        for (int ks = 0; ks < 2; ks++) {
            int kk = ks * 16;
            uint32_t ah[2][4], al[2][4], bh[4][2], bl[4][2];
            uint32_t acol = (uint32_t)(kk + a_k) * 2;
            uint32_t ad0 = sbase + OFF_AH + (warp_m * 32 + a_r) * (SSTRA * 2) + acol;
            uint32_t ad1 = ad0 + 16 * (SSTRA * 2);
            uint32_t bd0 = sbase + OFF_BH + (kk + b_kr) * (SSTRB * 2) +
                           (warp_n * 32 + b_nf) * 2;
            uint32_t bd1 = bd0 + 16 * 2;

            // ---- hi fragments ----
            ldsm_x4(ad0, ah[0][0], ah[0][1], ah[0][2], ah[0][3]);
            ldsm_x4(ad1, ah[1][0], ah[1][1], ah[1][2], ah[1][3]);
            {
                uint32_t r0, r1, r2, r3;
                ldsm_x4_t(bd0, r0, r1, r2, r3);
                bh[0][0] = r0; bh[0][1] = r1;
                bh[1][0] = r2; bh[1][1] = r3;
                ldsm_x4_t(bd1, r0, r1, r2, r3);
                bh[2][0] = r0; bh[2][1] = r1;
                bh[3][0] = r2; bh[3][1] = r3;
            }
            // ---- hi*hi MMAs (tensor pipe starts early) ----
#pragma unroll
            for (int mi = 0; mi < 2; mi++)
#pragma unroll
                for (int ni = 0; ni < 4; ni++)
                    mma_bf16(acc[mi][ni], ah[mi], bh[ni][0], bh[ni][1]);

            // ---- lo fragments (LSU overlaps tensor) ----
            ldsm_x4(ad0 + TA, al[0][0], al[0][1], al[0][2], al[0][3]);
            ldsm_x4(ad1 + TA, al[1][0], al[1][1], al[1][2], al[1][3]);
            {
                uint32_t r0, r1, r2, r3;
                ldsm_x4_t(bd0 + TB, r0, r1, r2, r3);
                bl[0][0] = r0; bl[0][1] = r1;
                bl[1][0] = r2; bl[1][1] = r3;
                ldsm_x4_t(bd1 + TB, r0, r1, r2, r3);
                bl[2][0] = r0; bl[2][1] = r1;
                bl[3][0] = r2; bl[3][1] = r3;
            }

            // ---- global prefetch for stage c+4 hides under MMA stream ----
            if (ks == 0) {
                if (c + NSTAGE - 1 < nch) {
                    uint32_t sb = smem + ((c + NSTAGE - 1) % NSTAGE) * STAGEB;
                    int k0 = (c + NSTAGE - 1) * BK;
                    if (tile_id == 0)      issue_A(sb + OFF_AH, Ah, brow, K, k0, t128);
                    else if (tile_id == 1) issue_A(sb + OFF_AL, Al, brow, K, k0, t128);
                    else if (tile_id == 2) issue_B(sb + OFF_BH, BhS, bcol, Nb, k0, t128);
                    else                   issue_B(sb + OFF_BL, BlS, bcol, Nb, k0, t128);
                }
                asm volatile("cp.async.commit_group;");  // exactly one per chunk
            }

            // ---- hi*lo and lo*hi MMAs ----
#pragma unroll
            for (int mi = 0; mi < 2; mi++)
#pragma unroll
                for (int ni = 0; ni < 4; ni++)
                    mma_bf16(acc[mi][ni], ah[mi], bl[ni][0], bl[ni][1]);
#pragma unroll
            for (int mi = 0; mi < 2; mi++)
#pragma unroll
                for (int ni = 0; ni < 4; ni++)
                    mma_bf16(acc[mi][ni], al[mi], bh[ni][0], bh[ni][1]);
        }
    }

    // ---- epilogue ----
    int qrow = lane >> 2;
    int qcol = (lane & 3) * 2;
#pragma unroll
    for (int mi = 0; mi < 2; mi++) {
#pragma unroll
        for (int h = 0; h < 2; h++) {
            int row = brow + warp_m * 32 + mi * 16 + qrow + h * 8;
#pragma unroll
            for (int ni = 0; ni < 4; ni++) {
                int col = bcol + warp_n * 32 + ni * 8 + qcol;
                size_t off = (size_t)row * Nout + col;
                float o0 = acc[mi][ni][h * 2];
                float o1 = acc[mi][ni][h * 2 + 1];
                if (MODE == 3) {
                    const float2 rv = *(const float2*)(res + off);
                    o0 += rv.x; o1 += rv.y;
                } else if (MODE == 4) {
                    const float2 rv = *(const float2*)(res + off);
                    const float2 gv = *(const float2*)(gate + off);
                    o0 = rv.x + gv.x * o0;
                    o1 = rv.y + gv.y * o1;
                } else if (epi == 1) {
                    o0 = 1.f / (1.f + expf(-o0));
                    o1 = 1.f / (1.f + expf(-o1));
                }
                if (epi == 2) {
                    o0 = fmaxf(o0, 0.f); o0 *= o0;
                    o1 = fmaxf(o1, 0.f); o1 *= o1;
                    __nv_bfloat16 h0 = __float2bfloat16(o0);
                    __nv_bfloat16 h1 = __float2bfloat16(o1);
                    __nv_bfloat162 hp; hp.x = h0; hp.y = h1;
                    __nv_bfloat162 lp;
                    lp.x = __float2bfloat16(o0 - __bfloat162float(h0));
                    lp.y = __float2bfloat16(o1 - __bfloat162float(h1));
                    *(__nv_bfloat162*)(outH + off) = hp;
                    *(__nv_bfloat162*)(outL + off) = lp;
                } else {
                    float2 ov = make_float2(o0, o1);
                    *(float2*)(outp + off) = ov;
                }
            }
        }
    }
}

// ---------------------------------------------------------------------------
// Chunk-parallel bidirectional WKV (3 kernels).
// ---------------------------------------------------------------------------
__global__ __launch_bounds__(256) void wkv_agg_k(
    const float* __restrict__ k, const float* __restrict__ v,
    const float* __restrict__ w,
    float* __restrict__ aFkv, float* __restrict__ aFk,
    float* __restrict__ aBkv, float* __restrict__ aBk) {
    int gid = blockIdx.x * blockDim.x + threadIdx.x;
    int c = gid & (C - 1);
    int ch = (gid >> 10) & (CH - 1);
    int b = gid >> 14;
    float d = expf(-expf(w[c]));
    size_t base = (size_t)b * T * C + (size_t)ch * CL * C + c;

    float fkv = 0.f, fk = 0.f, bkv = 0.f, bk = 0.f, pw = 1.f;
#pragma unroll 4
    for (int i = 0; i < CL; i++) {
        size_t o = base + (size_t)i * C;
        float ek = expf(k[o]);
        float kv = ek * v[o];
        fkv = fkv * d + kv;
        fk  = fk  * d + ek;
        bkv += kv * pw;
        bk  += ek * pw;
        pw *= d;
    }
    aFkv[gid] = fkv; aFk[gid] = fk;
    aBkv[gid] = bkv; aBk[gid] = bk;
}

__global__ __launch_bounds__(256) void wkv_scan_k(
    const float* __restrict__ w,
    const float* __restrict__ aFkv, const float* __restrict__ aFk,
    const float* __restrict__ aBkv, const float* __restrict__ aBk,
    float* __restrict__ iFkv, float* __restrict__ iFk,
    float* __restrict__ iBkv, float* __restrict__ iBk) {
    int gid = blockIdx.x * blockDim.x + threadIdx.x;
    int c = gid & (C - 1);
    int b = gid >> 10;
    float D = expf(-(float)CL * expf(w[c]));
    int base = b * CH * C + c;

    float skv = 0.f, sk = 0.f;
#pragma unroll
    for (int ch = 0; ch < CH; ch++) {
        int ai = base + ch * C;
        iFkv[ai] = skv; iFk[ai] = sk;
        skv = skv * D + aFkv[ai];
        sk  = sk  * D + aFk[ai];
    }
    skv = 0.f; sk = 0.f;
#pragma unroll
    for (int ch = CH - 1; ch >= 0; ch--) {
        int ai = base + ch * C;
        iBkv[ai] = skv; iBk[ai] = sk;
        skv = skv * D + aBkv[ai];
        sk  = sk  * D + aBk[ai];
    }
}

__global__ __launch_bounds__(256) void wkv_apply_k(
    const float* __restrict__ r, const float* __restrict__ k,
    const float* __restrict__ v, const float* __restrict__ w,
    const float* __restrict__ u,
    const float* __restrict__ iFkv, const float* __restrict__ iFk,
    const float* __restrict__ iBkv, const float* __restrict__ iBk,
    __nv_bfloat16* __restrict__ y_hi, __nv_bfloat16* __restrict__ y_lo,
    float* __restrict__ sakv, float* __restrict__ sak) {
    int gid = blockIdx.x * blockDim.x + threadIdx.x;
    int c = gid & (C - 1);
    int ch = (gid >> 10) & (CH - 1);
    int b = gid >> 14;
    float d = expf(-expf(w[c]));
    float eu = expf(u[c]);
    size_t base = (size_t)b * T * C + (size_t)ch * CL * C + c;

    float fkv = iFkv[gid], fk = iFk[gid];
#pragma unroll 4
    for (int i = 0; i < CL; i++) {
        size_t o = base + (size_t)i * C;
        float ek = expf(k[o]);
        float kv = ek * v[o];
        sakv[o] = fkv;
        sak[o]  = fk;
        fkv = fkv * d + kv;
        fk  = fk  * d + ek;
    }
    float bkv = iBkv[gid], bk = iBk[gid];
#pragma unroll 4
    for (int i = CL - 1; i >= 0; i--) {
        size_t o = base + (size_t)i * C;
        float vv = v[o];
        float ek = expf(k[o]);
        float kv = ek * vv;
        float num = sakv[o] + bkv + eu * vv;
        float den = sak[o]  + bk  + eu;
        float yv = r[o] * num / (den + 1e-8f);
        __nv_bfloat16 h = __float2bfloat16(yv);
        y_hi[o] = h;
        y_lo[o] = __float2bfloat16(yv - __bfloat162float(h));
        bkv = bkv * d + kv;
        bk  = bk  * d + ek;
    }
}

// ---------------------------------------------------------------------------
// Host launch
// ---------------------------------------------------------------------------
extern "C" void kernel_launch(void* const* d_in, const int* in_sizes, int n_in,
                              void* d_out, int out_size) {
    const int*   idx     = (const int*)  d_in[0];
    const float* emb     = (const float*)d_in[1];
    const float* ln1_w   = (const float*)d_in[2];
    const float* ln1_b   = (const float*)d_in[3];
    const float* Wr      = (const float*)d_in[4];
    const float* Wk      = (const float*)d_in[5];
    const float* Wv      = (const float*)d_in[6];
    const float* w_decay = (const float*)d_in[7];
    const float* u_bonus = (const float*)d_in[8];
    const float* Wo      = (const float*)d_in[9];
    const float* ln2_w   = (const float*)d_in[10];
    const float* ln2_b   = (const float*)d_in[11];
    const float* Wfk     = (const float*)d_in[12];
    const float* Wfv     = (const float*)d_in[13];
    const float* Wfr     = (const float*)d_in[14];
    const float* lnout_w = (const float*)d_in[15];
    const float* lnout_b = (const float*)d_in[16];
    const float* head_W  = (const float*)d_in[17];
    float* out = (float*)d_out;

    float *x, *r, *k, *v, *sa, *sb;
    float *aFkv, *aFk, *aBkv, *aBk, *iFkv, *iFk, *iBkv, *iBk;
    __nv_bfloat16 *wth, *wtl, *xnh, *xnl, *yh, *yl, *kfh, *kfl;
    cudaGetSymbolAddress((void**)&x,    g_x);
    cudaGetSymbolAddress((void**)&r,    g_r);
    cudaGetSymbolAddress((void**)&k,    g_k);
    cudaGetSymbolAddress((void**)&v,    g_v);
    cudaGetSymbolAddress((void**)&sa,   g_sakv);
    cudaGetSymbolAddress((void**)&sb,   g_sak);
    cudaGetSymbolAddress((void**)&wth,  g_wt_hi);
    cudaGetSymbolAddress((void**)&wtl,  g_wt_lo);
    cudaGetSymbolAddress((void**)&xnh,  g_xn_hi);
    cudaGetSymbolAddress((void**)&xnl,  g_xn_lo);
    cudaGetSymbolAddress((void**)&yh,   g_y_hi);
    cudaGetSymbolAddress((void**)&yl,   g_y_lo);
    cudaGetSymbolAddress((void**)&kfh,  g_kf_hi);
    cudaGetSymbolAddress((void**)&kfl,  g_kf_lo);
    cudaGetSymbolAddress((void**)&aFkv, g_aggFkv);
    cudaGetSymbolAddress((void**)&aFk,  g_aggFk);
    cudaGetSymbolAddress((void**)&aBkv, g_aggBkv);
    cudaGetSymbolAddress((void**)&aBk,  g_aggBk);
    cudaGetSymbolAddress((void**)&iFkv, g_iniFkv);
    cudaGetSymbolAddress((void**)&iFk,  g_iniFk);
    cudaGetSymbolAddress((void**)&iBkv, g_iniBkv);
    cudaGetSymbolAddress((void**)&iBk,  g_iniBk);

    cudaFuncSetAttribute(gemm_mma<0>, cudaFuncAttributeMaxDynamicSharedMemorySize, GEMM_SMEM);
    cudaFuncSetAttribute(gemm_mma<3>, cudaFuncAttributeMaxDynamicSharedMemorySize, GEMM_SMEM);
    cudaFuncSetAttribute(gemm_mma<4>, cudaFuncAttributeMaxDynamicSharedMemorySize, GEMM_SMEM);
    cudaFuncSetAttribute(gemm_mma<5>, cudaFuncAttributeMaxDynamicSharedMemorySize, GEMM_SMEM);
    cudaFuncSetAttribute(gemm_mma<6>, cudaFuncAttributeMaxDynamicSharedMemorySize, GEMM_SMEM);

    convert_all_k<<<4096, 256>>>((const float4*)Wr, (const float4*)Wk,
                                 (const float4*)Wv, (const float4*)Wo,
                                 (const float4*)Wfr, (const float4*)Wfk,
                                 (const float4*)Wfv, (const float4*)head_W,
                                 (uint4*)wth, (uint4*)wtl);

    embed_k<<<M, 256>>>(idx, emb, x);

    dim3 gRKV(M / 128, 24);        // fused r/k/v     (384 CTAs)
    dim3 gCM (M / 128, 40);        // fused gate/kf   (640 CTAs)
    dim3 gCCg(M / 128, C / 128);   // 16 x 8
    dim3 gCVg(M / 128, V / 128);   // 16 x 393

    for (int l = 0; l < L; l++) {
        size_t wcc = (size_t)l * C * C;
        size_t wcf = (size_t)l * C * F;
        const float* l1w = ln1_w + (size_t)l * C;
        const float* l1b = ln1_b + (size_t)l * C;
        const float* wd  = w_decay + (size_t)l * C;
        const float* ub  = u_bonus + (size_t)l * C;
        const float* l2w = ln2_w + (size_t)l * C;
        const float* l2b = ln2_b + (size_t)l * C;

        // time-mix
        layernorm_k<<<M, 256>>>(x, l1w, l1b, xnh, xnl);
        gemm_mma<5><<<gRKV, GTHREADS, GEMM_SMEM>>>(
            xnh, xnl, wth + O_WR + wcc, wtl + O_WR + wcc, nullptr, nullptr,
            r, nullptr, nullptr, k, v, C, C);
        wkv_agg_k<<<(B * CH * C) / 256, 256>>>(k, v, wd, aFkv, aFk, aBkv, aBk);
        wkv_scan_k<<<(B * C) / 256, 256>>>(wd, aFkv, aFk, aBkv, aBk,
                                           iFkv, iFk, iBkv, iBk);
        wkv_apply_k<<<(B * CH * C) / 256, 256>>>(r, k, v, wd, ub,
                                                 iFkv, iFk, iBkv, iBk,
                                                 yh, yl, sa, sb);
        gemm_mma<3><<<gCCg, GTHREADS, GEMM_SMEM>>>(
            yh, yl, wth + O_WO + wcc, wtl + O_WO + wcc, nullptr, nullptr,
            x, nullptr, nullptr, x, nullptr, C, C);

        // channel-mix
        layernorm_k<<<M, 256>>>(x, l2w, l2b, xnh, xnl);
        gemm_mma<6><<<gCM, GTHREADS, GEMM_SMEM>>>(
            xnh, xnl, wth + O_WFR + wcc, wtl + O_WFR + wcc,
            wth + O_WFK + wcf, wtl + O_WFK + wcf,
            r, kfh, kfl, nullptr, nullptr, F, C);
        gemm_mma<4><<<gCCg, GTHREADS, GEMM_SMEM>>>(
            kfh, kfl, wth + O_WFV + wcf, wtl + O_WFV + wcf, nullptr, nullptr,
            x, nullptr, nullptr, x, r, C, F);
    }

    layernorm_k<<<M, 256>>>(x, lnout_w, lnout_b, xnh, xnl);
    gemm_mma<0><<<gCVg, GTHREADS, GEMM_SMEM>>>(
        xnh, xnl, wth + O_HEAD, wtl + O_HEAD, nullptr, nullptr,
        out, nullptr, nullptr, nullptr, nullptr, V, C);
}